// round 1
// baseline (speedup 1.0000x reference)
#include <cuda_runtime.h>
#include <cuda_bf16.h>
#include <math.h>

// ---------------- problem constants ----------------
#define BB     4
#define TT     2048
#define DD     2048
#define HH     8
#define DK     128          // (D/2)/H
#define DV     256          // D/H
#define CHUNK  128
#define NCH    16           // T / CHUNK
#define MROWS  (BB*TT)      // 8192
#define DHALF  (DD/2)       // 1024
#define SCALING 0.0625f     // (D/H)^-0.5 = 1/16
#define INV_NORM_GK (1.0f/16.0f)

// ---------------- scratch (device globals; no runtime alloc) ----------------
__device__ float g_Q  [(size_t)MROWS * DHALF];
__device__ float g_K  [(size_t)MROWS * DHALF];
__device__ float g_GK [(size_t)MROWS * DHALF];
__device__ float g_KD [(size_t)MROWS * DHALF];
__device__ float g_KG1[(size_t)MROWS * 16];
__device__ float g_DEC[(size_t)BB * NCH * DHALF];
__device__ float g_V  [(size_t)MROWS * DD];
__device__ float g_G  [(size_t)MROWS * DD];
__device__ float g_O  [(size_t)MROWS * DD];
__device__ float g_PRE[(size_t)MROWS * DD];

// ======================================================================
// Generic SGEMM: C = alpha * A(MxK) @ B(KxN) (+ bias). 128x128x16 tiles,
// 256 threads, 8x8 microtile. M%128==0, K%16==0, N%4==0 required.
// ======================================================================
__global__ __launch_bounds__(256, 2)
void sgemm128(const float* __restrict__ A, const float* __restrict__ B,
              float* __restrict__ C, int M, int N, int K,
              float alpha, const float* __restrict__ bias)
{
    __shared__ float As[16][136];   // transposed A tile, padded
    __shared__ float Bs[16][128];

    const int tid = threadIdx.x;
    const int tx = tid & 15, ty = tid >> 4;
    const int row0 = blockIdx.y * 128;
    const int col0 = blockIdx.x * 128;

    float acc[8][8];
#pragma unroll
    for (int r = 0; r < 8; r++)
#pragma unroll
        for (int c = 0; c < 8; c++) acc[r][c] = 0.f;

    for (int k0 = 0; k0 < K; k0 += 16) {
        // A tile: 128 rows x 16 cols  (512 float4, 2 per thread), transpose into As
#pragma unroll
        for (int l = 0; l < 2; l++) {
            int idx = tid + l * 256;
            int r = idx >> 2;            // 0..127
            int c4 = (idx & 3) << 2;     // 0,4,8,12
            float4 f = *(const float4*)&A[(size_t)(row0 + r) * K + k0 + c4];
            As[c4 + 0][r] = f.x; As[c4 + 1][r] = f.y;
            As[c4 + 2][r] = f.z; As[c4 + 3][r] = f.w;
        }
        // B tile: 16 rows x 128 cols (512 float4, 2 per thread)
#pragma unroll
        for (int l = 0; l < 2; l++) {
            int idx = tid + l * 256;
            int r = idx >> 5;            // 0..15
            int c4 = (idx & 31) << 2;    // 0..124
            int gc = col0 + c4;
            float4 f = make_float4(0.f, 0.f, 0.f, 0.f);
            if (gc < N) f = *(const float4*)&B[(size_t)(k0 + r) * N + gc];
            *(float4*)&Bs[r][c4] = f;
        }
        __syncthreads();

#pragma unroll
        for (int kk = 0; kk < 16; kk++) {
            float a[8], b[8];
            float4 a0 = *(float4*)&As[kk][ty * 8];
            float4 a1 = *(float4*)&As[kk][ty * 8 + 4];
            float4 b0 = *(float4*)&Bs[kk][tx * 8];
            float4 b1 = *(float4*)&Bs[kk][tx * 8 + 4];
            a[0]=a0.x; a[1]=a0.y; a[2]=a0.z; a[3]=a0.w;
            a[4]=a1.x; a[5]=a1.y; a[6]=a1.z; a[7]=a1.w;
            b[0]=b0.x; b[1]=b0.y; b[2]=b0.z; b[3]=b0.w;
            b[4]=b1.x; b[5]=b1.y; b[6]=b1.z; b[7]=b1.w;
#pragma unroll
            for (int r = 0; r < 8; r++)
#pragma unroll
                for (int c = 0; c < 8; c++)
                    acc[r][c] = fmaf(a[r], b[c], acc[r][c]);
        }
        __syncthreads();
    }

    // epilogue
#pragma unroll
    for (int r = 0; r < 8; r++) {
        int row = row0 + ty * 8 + r;
#pragma unroll
        for (int c4 = 0; c4 < 8; c4 += 4) {
            int col = col0 + tx * 8 + c4;
            if (col < N) {
                float4 o;
                o.x = alpha * acc[r][c4 + 0];
                o.y = alpha * acc[r][c4 + 1];
                o.z = alpha * acc[r][c4 + 2];
                o.w = alpha * acc[r][c4 + 3];
                if (bias) {
                    o.x += bias[col + 0]; o.y += bias[col + 1];
                    o.z += bias[col + 2]; o.w += bias[col + 3];
                }
                *(float4*)&C[(size_t)row * N + col] = o;
            }
        }
    }
}

// ======================================================================
// gk = log_sigmoid(KG1 @ Wkg2 + bkg2) / 16    (K=16 tiny GEMM fused)
// one block (128 thr) per row m
// ======================================================================
__global__ void gk_kernel(const float* __restrict__ KG1,
                          const float* __restrict__ W2,
                          const float* __restrict__ b2,
                          float* __restrict__ GK)
{
    __shared__ float a[16];
    int m = blockIdx.x;
    if (threadIdx.x < 16) a[threadIdx.x] = KG1[(size_t)m * 16 + threadIdx.x];
    __syncthreads();
    for (int c = threadIdx.x; c < DHALF; c += 128) {
        float z = b2[c];
#pragma unroll
        for (int r = 0; r < 16; r++) z = fmaf(a[r], W2[(size_t)r * DHALF + c], z);
        float ls = (z >= 0.f) ? -log1pf(expf(-z)) : (z - log1pf(expf(z)));
        GK[(size_t)m * DHALF + c] = ls * INV_NORM_GK;
    }
}

// ======================================================================
// Decay precompute: per (batch, chunk, column) do the in-chunk cumsum and
// produce  Q <- q*exp(gc),  K <- k*exp(-gc),  KD = k*exp(gs-gc),  DEC=exp(gs)
// one thread per column; 65536 threads total.
// ======================================================================
__global__ void prep_kernel(float* __restrict__ Q, float* __restrict__ Kx,
                            const float* __restrict__ GK,
                            float* __restrict__ KD, float* __restrict__ DEC)
{
    int g = blockIdx.x * blockDim.x + threadIdx.x;       // 0..65535
    int col = g & (DHALF - 1);
    int bc  = g >> 10;                                   // bb*16 + chunk
    int row0 = ((bc >> 4) * TT) + ((bc & 15) * CHUNK);
    size_t base = (size_t)row0 * DHALF + col;

    float gs = 0.f;
#pragma unroll 4
    for (int i = 0; i < CHUNK; i++) gs += GK[base + (size_t)i * DHALF];

    float gc = 0.f;
    for (int i = 0; i < CHUNK; i++) {
        size_t idx = base + (size_t)i * DHALF;
        gc += GK[idx];
        Q[idx] *= expf(gc);
        float kv = Kx[idx];
        KD[idx] = kv * expf(gs - gc);
        Kx[idx] = kv * expf(-gc);
    }
    DEC[(size_t)bc * DHALF + col] = expf(gs);
}

// ======================================================================
// GLA main: one block per (b, h, dv-slice of 64). Sequential over 16 chunks.
// smem: qdt[128][128] (transposed qd), At[128][128] (A^T, later kd),
//       S[128][64], vs[128][64] (first 8KB aliased as kexp tile kt[16][128]).
// 256 threads.
// ======================================================================
__global__ __launch_bounds__(256, 1)
void gla_kernel(const float* __restrict__ Q, const float* __restrict__ Kx,
                const float* __restrict__ KD, const float* __restrict__ V,
                const float* __restrict__ DEC, float* __restrict__ O)
{
    extern __shared__ float sm[];
    float* qdt = sm;                       // 128*128
    float* At  = sm + 128 * 128;           // 128*128 (A^T; later kd row-major)
    float* S   = sm + 2 * 128 * 128;       // 128*64
    float* vs  = sm + 2 * 128 * 128 + 128 * 64;  // 128*64 ; kt alias (16*128)
    float* kt  = vs;
    __shared__ float dec[128];

    const int tid = threadIdx.x;
    const int tx = tid & 15, ty = tid >> 4;
    const int bb = blockIdx.z, h = blockIdx.y, vsl = blockIdx.x;
    const int colQ = h * DK;
    const int colV = h * DV + vsl * 64;

    for (int i = tid; i < 128 * 64; i += 256) S[i] = 0.f;

    for (int ch = 0; ch < NCH; ch++) {
        const int m0 = bb * TT + ch * CHUNK;
        __syncthreads();   // previous chunk fully done (S/vs/At reads)

        // load qd chunk transposed: qdt[d][i]
        for (int idx = tid; idx < 128 * 32; idx += 256) {
            int r = idx >> 5, c4 = (idx & 31) << 2;
            float4 f = *(const float4*)&Q[(size_t)(m0 + r) * DHALF + colQ + c4];
            qdt[(c4 + 0) * 128 + r] = f.x; qdt[(c4 + 1) * 128 + r] = f.y;
            qdt[(c4 + 2) * 128 + r] = f.z; qdt[(c4 + 3) * 128 + r] = f.w;
        }

        // ---- A = qd @ kexp^T  (128x128x128), stream kexp in 16-wide tiles
        float acc[8][8];
#pragma unroll
        for (int r = 0; r < 8; r++)
#pragma unroll
            for (int c = 0; c < 8; c++) acc[r][c] = 0.f;

        for (int dt = 0; dt < 8; dt++) {
            __syncthreads();   // qdt loaded (dt==0) / previous kt consumed
            for (int idx = tid; idx < 128 * 4; idx += 256) {
                int j = idx >> 2, c4 = (idx & 3) << 2;
                float4 f = *(const float4*)&Kx[(size_t)(m0 + j) * DHALF + colQ + dt * 16 + c4];
                kt[(c4 + 0) * 128 + j] = f.x; kt[(c4 + 1) * 128 + j] = f.y;
                kt[(c4 + 2) * 128 + j] = f.z; kt[(c4 + 3) * 128 + j] = f.w;
            }
            __syncthreads();
#pragma unroll
            for (int dl = 0; dl < 16; dl++) {
                int d = dt * 16 + dl;
                float a[8], b[8];
                float4 a0 = *(float4*)&qdt[d * 128 + ty * 8];
                float4 a1 = *(float4*)&qdt[d * 128 + ty * 8 + 4];
                float4 b0 = *(float4*)&kt[dl * 128 + tx * 8];
                float4 b1 = *(float4*)&kt[dl * 128 + tx * 8 + 4];
                a[0]=a0.x;a[1]=a0.y;a[2]=a0.z;a[3]=a0.w;
                a[4]=a1.x;a[5]=a1.y;a[6]=a1.z;a[7]=a1.w;
                b[0]=b0.x;b[1]=b0.y;b[2]=b0.z;b[3]=b0.w;
                b[4]=b1.x;b[5]=b1.y;b[6]=b1.z;b[7]=b1.w;
#pragma unroll
                for (int r = 0; r < 8; r++)
#pragma unroll
                    for (int c = 0; c < 8; c++)
                        acc[r][c] = fmaf(a[r], b[c], acc[r][c]);
            }
        }
        // masked store A^T
#pragma unroll
        for (int r = 0; r < 8; r++) {
            int i = ty * 8 + r;
#pragma unroll
            for (int c = 0; c < 8; c++) {
                int j = tx * 8 + c;
                At[j * 128 + i] = (j <= i) ? acc[r][c] : 0.f;
            }
        }
        __syncthreads();   // A^T visible; kt region free

        // load v slice (overwrites kt alias region)
        for (int idx = tid; idx < 128 * 16; idx += 256) {
            int j = idx >> 4, c4 = (idx & 15) << 2;
            *(float4*)&vs[j * 64 + c4] =
                *(const float4*)&V[(size_t)(m0 + j) * DD + colV + c4];
        }
        __syncthreads();

        // ---- o = tril(A) @ v + qd @ S   (128x64)
        float oa[8][4];
#pragma unroll
        for (int r = 0; r < 8; r++)
#pragma unroll
            for (int c = 0; c < 4; c++) oa[r][c] = 0.f;

        for (int j = 0; j < 128; j++) {
            float a[8];
            float4 a0 = *(float4*)&At[j * 128 + ty * 8];
            float4 a1 = *(float4*)&At[j * 128 + ty * 8 + 4];
            float4 b  = *(float4*)&vs[j * 64 + tx * 4];
            a[0]=a0.x;a[1]=a0.y;a[2]=a0.z;a[3]=a0.w;
            a[4]=a1.x;a[5]=a1.y;a[6]=a1.z;a[7]=a1.w;
#pragma unroll
            for (int r = 0; r < 8; r++) {
                oa[r][0] = fmaf(a[r], b.x, oa[r][0]);
                oa[r][1] = fmaf(a[r], b.y, oa[r][1]);
                oa[r][2] = fmaf(a[r], b.z, oa[r][2]);
                oa[r][3] = fmaf(a[r], b.w, oa[r][3]);
            }
        }
        for (int d = 0; d < 128; d++) {
            float a[8];
            float4 a0 = *(float4*)&qdt[d * 128 + ty * 8];
            float4 a1 = *(float4*)&qdt[d * 128 + ty * 8 + 4];
            float4 b  = *(float4*)&S[d * 64 + tx * 4];
            a[0]=a0.x;a[1]=a0.y;a[2]=a0.z;a[3]=a0.w;
            a[4]=a1.x;a[5]=a1.y;a[6]=a1.z;a[7]=a1.w;
#pragma unroll
            for (int r = 0; r < 8; r++) {
                oa[r][0] = fmaf(a[r], b.x, oa[r][0]);
                oa[r][1] = fmaf(a[r], b.y, oa[r][1]);
                oa[r][2] = fmaf(a[r], b.z, oa[r][2]);
                oa[r][3] = fmaf(a[r], b.w, oa[r][3]);
            }
        }
#pragma unroll
        for (int r = 0; r < 8; r++) {
            int row = m0 + ty * 8 + r;
            float4 o; o.x = oa[r][0]; o.y = oa[r][1]; o.z = oa[r][2]; o.w = oa[r][3];
            *(float4*)&O[(size_t)row * DD + colV + tx * 4] = o;
        }
        __syncthreads();   // done reading At/S -> safe to overwrite At with kd

        // load kd chunk (row-major into At region) + decay vector
        for (int idx = tid; idx < 128 * 32; idx += 256) {
            int j = idx >> 5, c4 = (idx & 31) << 2;
            *(float4*)&At[j * 128 + c4] =
                *(const float4*)&KD[(size_t)(m0 + j) * DHALF + colQ + c4];
        }
        if (tid < 128) dec[tid] = DEC[(size_t)(bb * NCH + ch) * DHALF + colQ + tid];
        __syncthreads();

        // ---- S = diag(dec) S + kd^T @ v
        float sa[8][4];
#pragma unroll
        for (int r = 0; r < 8; r++) {
            int d = ty * 8 + r;
            float dv = dec[d];
#pragma unroll
            for (int c = 0; c < 4; c++)
                sa[r][c] = dv * S[d * 64 + tx * 4 + c];
        }
        for (int j = 0; j < 128; j++) {
            float a[8];
            float4 a0 = *(float4*)&At[j * 128 + ty * 8];
            float4 a1 = *(float4*)&At[j * 128 + ty * 8 + 4];
            float4 b  = *(float4*)&vs[j * 64 + tx * 4];
            a[0]=a0.x;a[1]=a0.y;a[2]=a0.z;a[3]=a0.w;
            a[4]=a1.x;a[5]=a1.y;a[6]=a1.z;a[7]=a1.w;
#pragma unroll
            for (int r = 0; r < 8; r++) {
                sa[r][0] = fmaf(a[r], b.x, sa[r][0]);
                sa[r][1] = fmaf(a[r], b.y, sa[r][1]);
                sa[r][2] = fmaf(a[r], b.z, sa[r][2]);
                sa[r][3] = fmaf(a[r], b.w, sa[r][3]);
            }
        }
#pragma unroll
        for (int r = 0; r < 8; r++) {
            int d = ty * 8 + r;
            float4 o; o.x = sa[r][0]; o.y = sa[r][1]; o.z = sa[r][2]; o.w = sa[r][3];
            *(float4*)&S[d * 64 + tx * 4] = o;
        }
    }
}

// ======================================================================
// GroupNorm(dv=256, no affine) then * silu(g) -> PRE
// one block (256 thr) per (row m, head h)
// ======================================================================
__global__ void norm_gate_kernel(const float* __restrict__ O,
                                 const float* __restrict__ G,
                                 float* __restrict__ PRE)
{
    int m = blockIdx.x, h = blockIdx.y;
    int tid = threadIdx.x;
    size_t idx = (size_t)m * DD + h * DV + tid;
    float v = O[idx];
    float s = v, s2 = v * v;
#pragma unroll
    for (int off = 16; off; off >>= 1) {
        s  += __shfl_xor_sync(0xFFFFFFFFu, s,  off);
        s2 += __shfl_xor_sync(0xFFFFFFFFu, s2, off);
    }
    __shared__ float ws[8], ws2[8];
    int w = tid >> 5, l = tid & 31;
    if (l == 0) { ws[w] = s; ws2[w] = s2; }
    __syncthreads();
    float ts = 0.f, ts2 = 0.f;
#pragma unroll
    for (int i = 0; i < 8; i++) { ts += ws[i]; ts2 += ws2[i]; }
    float mu = ts * (1.f / 256.f);
    float var = ts2 * (1.f / 256.f) - mu * mu;
    float nv = (v - mu) * rsqrtf(var + 1e-5f);
    float gt = G[idx];
    float sg = gt / (1.f + expf(-gt));
    PRE[idx] = sg * nv;
}

// ======================================================================
extern "C" void kernel_launch(void* const* d_in, const int* in_sizes, int n_in,
                              void* d_out, int out_size)
{
    const float* x    = (const float*)d_in[0];
    const float* Wq   = (const float*)d_in[1];
    const float* Wk   = (const float*)d_in[2];
    const float* Wkg1 = (const float*)d_in[3];
    const float* Wkg2 = (const float*)d_in[4];
    const float* bkg2 = (const float*)d_in[5];
    const float* Wv   = (const float*)d_in[6];
    const float* Wg   = (const float*)d_in[7];
    const float* bg   = (const float*)d_in[8];
    const float* Wo   = (const float*)d_in[9];
    float* out = (float*)d_out;

    float *pQ, *pK, *pGK, *pKD, *pKG1, *pDEC, *pV, *pG, *pO, *pPRE;
    cudaGetSymbolAddress((void**)&pQ,   g_Q);
    cudaGetSymbolAddress((void**)&pK,   g_K);
    cudaGetSymbolAddress((void**)&pGK,  g_GK);
    cudaGetSymbolAddress((void**)&pKD,  g_KD);
    cudaGetSymbolAddress((void**)&pKG1, g_KG1);
    cudaGetSymbolAddress((void**)&pDEC, g_DEC);
    cudaGetSymbolAddress((void**)&pV,   g_V);
    cudaGetSymbolAddress((void**)&pG,   g_G);
    cudaGetSymbolAddress((void**)&pO,   g_O);
    cudaGetSymbolAddress((void**)&pPRE, g_PRE);

    cudaFuncSetAttribute(gla_kernel,
                         cudaFuncAttributeMaxDynamicSharedMemorySize, 196608);

    dim3 thr(256);
    // projections
    sgemm128<<<dim3(DHALF / 128, MROWS / 128), thr>>>(x, Wq, pQ,  MROWS, DHALF, DD, 1.0f,    nullptr);
    sgemm128<<<dim3(DHALF / 128, MROWS / 128), thr>>>(x, Wk, pK,  MROWS, DHALF, DD, SCALING, nullptr);
    sgemm128<<<dim3(1,           MROWS / 128), thr>>>(x, Wkg1, pKG1, MROWS, 16, DD, 1.0f,   nullptr);
    sgemm128<<<dim3(DD / 128,    MROWS / 128), thr>>>(x, Wv, pV,  MROWS, DD,    DD, 1.0f,    nullptr);
    sgemm128<<<dim3(DD / 128,    MROWS / 128), thr>>>(x, Wg, pG,  MROWS, DD,    DD, 1.0f,    bg);

    // gk
    gk_kernel<<<MROWS, 128>>>(pKG1, Wkg2, bkg2, pGK);

    // decay precompute (in-place transforms of Q, K)
    prep_kernel<<<256, 256>>>(pQ, pK, pGK, pKD, pDEC);

    // chunked GLA
    gla_kernel<<<dim3(DV / 64, HH, BB), 256, 196608>>>(pQ, pK, pKD, pV, pDEC, pO);

    // groupnorm + silu gate
    norm_gate_kernel<<<dim3(MROWS, HH), 256>>>(pO, pG, pPRE);

    // output projection
    sgemm128<<<dim3(DD / 128, MROWS / 128), thr>>>(pPRE, Wo, out, MROWS, DD, DD, 1.0f, nullptr);
}

// round 3
// speedup vs baseline: 2.1860x; 2.1860x over previous
#include <cuda_runtime.h>
#include <cuda_bf16.h>
#include <math.h>
#include <stdint.h>

// ---------------- problem constants ----------------
#define BB     4
#define TT     2048
#define DD     2048
#define HH     8
#define DK     128
#define DV     256
#define CHUNK  128
#define NCH    16
#define MROWS  (BB*TT)      // 8192
#define DHALF  (DD/2)       // 1024
#define SCALING 0.0625f
#define INV_NORM_GK (1.0f/16.0f)

// ---------------- scratch ----------------
__device__ float g_Q  [(size_t)MROWS * DHALF];
__device__ float g_K  [(size_t)MROWS * DHALF];
__device__ float g_GK [(size_t)MROWS * DHALF];
__device__ float g_KD [(size_t)MROWS * DHALF];
__device__ float g_KG1[(size_t)MROWS * 16];
__device__ float g_DEC[(size_t)BB * NCH * DHALF];
__device__ float g_V  [(size_t)MROWS * DD];
__device__ float g_G  [(size_t)MROWS * DD];
__device__ float g_O  [(size_t)MROWS * DD];
__device__ __nv_bfloat16 g_XH [(size_t)MROWS * DD];
__device__ __nv_bfloat16 g_XL [(size_t)MROWS * DD];
__device__ __nv_bfloat16 g_WTH[(size_t)DD * DD];
__device__ __nv_bfloat16 g_WTL[(size_t)DD * DD];
__device__ __nv_bfloat16 g_PH [(size_t)MROWS * DD];
__device__ __nv_bfloat16 g_PL [(size_t)MROWS * DD];

// ================= helpers =================
__device__ __forceinline__ uint32_t smem_u32(const void* p) {
    uint32_t a;
    asm("{ .reg .u64 t; cvta.to.shared.u64 t, %1; cvt.u32.u64 %0, t; }" : "=r"(a) : "l"(p));
    return a;
}
__device__ __forceinline__ void cpasync16(uint32_t dst, const void* src) {
    asm volatile("cp.async.cg.shared.global [%0], [%1], 16;" :: "r"(dst), "l"(src) : "memory");
}
__device__ __forceinline__ void ldsm_x4(uint32_t* r, uint32_t addr) {
    asm volatile("ldmatrix.sync.aligned.m8n8.x4.shared.b16 {%0,%1,%2,%3}, [%4];"
                 : "=r"(r[0]), "=r"(r[1]), "=r"(r[2]), "=r"(r[3]) : "r"(addr));
}
__device__ __forceinline__ void mma16816(float* c, const uint32_t* a, const uint32_t* b) {
    asm volatile(
        "mma.sync.aligned.m16n8k16.row.col.f32.bf16.bf16.f32 "
        "{%0,%1,%2,%3}, {%4,%5,%6,%7}, {%8,%9}, {%0,%1,%2,%3};"
        : "+f"(c[0]), "+f"(c[1]), "+f"(c[2]), "+f"(c[3])
        : "r"(a[0]), "r"(a[1]), "r"(a[2]), "r"(a[3]), "r"(b[0]), "r"(b[1]));
}
static __device__ __forceinline__ uint32_t sw128(uint32_t o) { return o ^ ((o >> 3) & 0x70); }

// ======================================================================
// bf16x3 fp32-emulated GEMM on mma.sync (HMMA).
// C[M,N] = alpha * (A @ B^T) (+bias), with A = Ahi+Alo [M,K] row-major,
// B = Bhi+Blo [N,K] row-major (weight transposed). 3 accumulation passes:
// hi*hi + hi*lo + lo*hi. Block tile 128x128, KBLOCK=64, 2-stage cp.async.
// ======================================================================
__global__ __launch_bounds__(256, 2)
void gemm_mma(const __nv_bfloat16* __restrict__ Ahi, const __nv_bfloat16* __restrict__ Alo,
              const __nv_bfloat16* __restrict__ Bhi, const __nv_bfloat16* __restrict__ Blo,
              float* __restrict__ C, int M, int N, int K,
              float alpha, const float* __restrict__ bias)
{
    extern __shared__ char smem[];
    const uint32_t sbase = smem_u32(smem);
    const int tid = threadIdx.x;
    const int wid = tid >> 5, lane = tid & 31;
    const int m0 = blockIdx.y * 128;
    const int n0 = blockIdx.x * 128;
    const int mw = (wid & 1) * 64;       // warp M offset
    const int nw = (wid >> 1) * 32;      // warp N offset

    const int KC = K >> 6;               // 64-wide K chunks per pass
    const int TOT = 3 * KC;

    float acc[4][4][4];
#pragma unroll
    for (int i = 0; i < 4; i++)
#pragma unroll
        for (int j = 0; j < 4; j++)
#pragma unroll
            for (int l = 0; l < 4; l++) acc[i][j][l] = 0.f;

    // per-thread load coords (4 x 16B for A, 4 for B per stage)
    const int lrow = tid >> 3;           // 0..31 (row step 32)
    const int lch  = (tid & 7) << 4;     // byte chunk in 128B row
    const int lel  = (tid & 7) << 3;     // element offset

    auto issue = [&](int it) {
        const int p = it / KC;
        const int k0 = (it - p * KC) << 6;
        const __nv_bfloat16* Ap = (p == 2) ? Alo : Ahi;
        const __nv_bfloat16* Bp = (p == 1) ? Blo : Bhi;
        const uint32_t sA = sbase + (uint32_t)(it & 1) * 32768u;
        const uint32_t sB = sA + 16384u;
#pragma unroll
        for (int l = 0; l < 4; l++) {
            int row = lrow + l * 32;
            uint32_t dst = sw128((uint32_t)(row << 7) + lch);
            cpasync16(sA + dst, Ap + (size_t)(m0 + row) * K + k0 + lel);
            cpasync16(sB + dst, Bp + (size_t)(n0 + row) * K + k0 + lel);
        }
        asm volatile("cp.async.commit_group;" ::: "memory");
    };

    issue(0);
    for (int it = 0; it < TOT; it++) {
        if (it + 1 < TOT) {
            issue(it + 1);
            asm volatile("cp.async.wait_group 1;" ::: "memory");
        } else {
            asm volatile("cp.async.wait_group 0;" ::: "memory");
        }
        __syncthreads();

        const uint32_t sA = sbase + (uint32_t)(it & 1) * 32768u;
        const uint32_t sB = sA + 16384u;
#pragma unroll
        for (int ks = 0; ks < 4; ks++) {
            uint32_t af[4][4], bf[4][2];
#pragma unroll
            for (int mf = 0; mf < 4; mf++) {
                int row = mw + mf * 16 + (lane & 15);
                uint32_t bo = (uint32_t)(row << 7) + (uint32_t)(ks << 5) + ((lane >> 4) << 4);
                ldsm_x4(af[mf], sA + sw128(bo));
            }
#pragma unroll
            for (int half = 0; half < 2; half++) {
                int i = lane >> 3;
                int row = nw + half * 16 + ((i >> 1) << 3) + (lane & 7);
                uint32_t bo = (uint32_t)(row << 7) + (uint32_t)(ks << 5) + ((i & 1) << 4);
                uint32_t r[4];
                ldsm_x4(r, sB + sw128(bo));
                bf[half * 2][0] = r[0];     bf[half * 2][1] = r[1];
                bf[half * 2 + 1][0] = r[2]; bf[half * 2 + 1][1] = r[3];
            }
#pragma unroll
            for (int mf = 0; mf < 4; mf++)
#pragma unroll
                for (int nf = 0; nf < 4; nf++)
                    mma16816(acc[mf][nf], af[mf], bf[nf]);
        }
        __syncthreads();
    }

    // epilogue
    const int rb = m0 + mw + (lane >> 2);
    const int cb = n0 + nw + ((lane & 3) << 1);
#pragma unroll
    for (int mf = 0; mf < 4; mf++) {
#pragma unroll
        for (int half = 0; half < 2; half++) {
            int row = rb + mf * 16 + half * 8;
            float* cp = C + (size_t)row * N;
#pragma unroll
            for (int nf = 0; nf < 4; nf++) {
                int col = cb + nf * 8;
                float2 v;
                v.x = alpha * acc[mf][nf][half * 2 + 0];
                v.y = alpha * acc[mf][nf][half * 2 + 1];
                if (bias) { v.x += bias[col]; v.y += bias[col + 1]; }
                *(float2*)(cp + col) = v;
            }
        }
    }
}

// ======================================================================
// split x -> bf16 hi/lo
// ======================================================================
__global__ void xsplit(const float4* __restrict__ X, __nv_bfloat16* __restrict__ H,
                       __nv_bfloat16* __restrict__ L, int n4)
{
    int i = blockIdx.x * blockDim.x + threadIdx.x;
    if (i >= n4) return;
    float4 v = X[i];
    __nv_bfloat16 h0 = __float2bfloat16(v.x), h1 = __float2bfloat16(v.y);
    __nv_bfloat16 h2 = __float2bfloat16(v.z), h3 = __float2bfloat16(v.w);
    __nv_bfloat16 l0 = __float2bfloat16(v.x - __bfloat162float(h0));
    __nv_bfloat16 l1 = __float2bfloat16(v.y - __bfloat162float(h1));
    __nv_bfloat16 l2 = __float2bfloat16(v.z - __bfloat162float(h2));
    __nv_bfloat16 l3 = __float2bfloat16(v.w - __bfloat162float(h3));
    __nv_bfloat162* Hp = (__nv_bfloat162*)H;
    __nv_bfloat162* Lp = (__nv_bfloat162*)L;
    Hp[i * 2]     = __nv_bfloat162(h0, h1);
    Hp[i * 2 + 1] = __nv_bfloat162(h2, h3);
    Lp[i * 2]     = __nv_bfloat162(l0, l1);
    Lp[i * 2 + 1] = __nv_bfloat162(l2, l3);
}

// ======================================================================
// transpose W [K,N] -> Th/Tl [N,K] bf16 split
// ======================================================================
__global__ void wsplit_t(const float* __restrict__ W, __nv_bfloat16* __restrict__ Th,
                         __nv_bfloat16* __restrict__ Tl, int K, int N)
{
    __shared__ float t[32][33];
    const int n0 = blockIdx.x * 32, k0 = blockIdx.y * 32;
    const int tx = threadIdx.x, ty = threadIdx.y;
#pragma unroll
    for (int i = 0; i < 4; i++) {
        int k = ty + i * 8;
        t[k][tx] = W[(size_t)(k0 + k) * N + n0 + tx];
    }
    __syncthreads();
#pragma unroll
    for (int i = 0; i < 4; i++) {
        int n = ty + i * 8;
        float v = t[tx][n];
        __nv_bfloat16 h = __float2bfloat16(v);
        size_t oi = (size_t)(n0 + n) * K + k0 + tx;
        Th[oi] = h;
        Tl[oi] = __float2bfloat16(v - __bfloat162float(h));
    }
}

// ======================================================================
// fp32 SGEMM (only for tiny x @ Wkg1, N=16)
// ======================================================================
__global__ __launch_bounds__(256, 2)
void sgemm128(const float* __restrict__ A, const float* __restrict__ B,
              float* __restrict__ C, int M, int N, int K,
              float alpha, const float* __restrict__ bias)
{
    __shared__ float As[16][136];
    __shared__ float Bs[16][128];
    const int tid = threadIdx.x;
    const int tx = tid & 15, ty = tid >> 4;
    const int row0 = blockIdx.y * 128;
    const int col0 = blockIdx.x * 128;

    float acc[8][8];
#pragma unroll
    for (int r = 0; r < 8; r++)
#pragma unroll
        for (int c = 0; c < 8; c++) acc[r][c] = 0.f;

    for (int k0 = 0; k0 < K; k0 += 16) {
#pragma unroll
        for (int l = 0; l < 2; l++) {
            int idx = tid + l * 256;
            int r = idx >> 2, c4 = (idx & 3) << 2;
            float4 f = *(const float4*)&A[(size_t)(row0 + r) * K + k0 + c4];
            As[c4 + 0][r] = f.x; As[c4 + 1][r] = f.y;
            As[c4 + 2][r] = f.z; As[c4 + 3][r] = f.w;
        }
#pragma unroll
        for (int l = 0; l < 2; l++) {
            int idx = tid + l * 256;
            int r = idx >> 5, c4 = (idx & 31) << 2;
            int gc = col0 + c4;
            float4 f = make_float4(0.f, 0.f, 0.f, 0.f);
            if (gc < N) f = *(const float4*)&B[(size_t)(k0 + r) * N + gc];
            *(float4*)&Bs[r][c4] = f;
        }
        __syncthreads();
#pragma unroll
        for (int kk = 0; kk < 16; kk++) {
            float a[8], b[8];
            float4 a0 = *(float4*)&As[kk][ty * 8];
            float4 a1 = *(float4*)&As[kk][ty * 8 + 4];
            float4 b0 = *(float4*)&Bs[kk][tx * 8];
            float4 b1 = *(float4*)&Bs[kk][tx * 8 + 4];
            a[0]=a0.x; a[1]=a0.y; a[2]=a0.z; a[3]=a0.w;
            a[4]=a1.x; a[5]=a1.y; a[6]=a1.z; a[7]=a1.w;
            b[0]=b0.x; b[1]=b0.y; b[2]=b0.z; b[3]=b0.w;
            b[4]=b1.x; b[5]=b1.y; b[6]=b1.z; b[7]=b1.w;
#pragma unroll
            for (int r = 0; r < 8; r++)
#pragma unroll
                for (int c = 0; c < 8; c++)
                    acc[r][c] = fmaf(a[r], b[c], acc[r][c]);
        }
        __syncthreads();
    }
#pragma unroll
    for (int r = 0; r < 8; r++) {
        int row = row0 + ty * 8 + r;
#pragma unroll
        for (int c4 = 0; c4 < 8; c4 += 4) {
            int col = col0 + tx * 8 + c4;
            if (col < N) {
                float4 o;
                o.x = alpha * acc[r][c4 + 0];
                o.y = alpha * acc[r][c4 + 1];
                o.z = alpha * acc[r][c4 + 2];
                o.w = alpha * acc[r][c4 + 3];
                if (bias) {
                    o.x += bias[col + 0]; o.y += bias[col + 1];
                    o.z += bias[col + 2]; o.w += bias[col + 3];
                }
                *(float4*)&C[(size_t)row * N + col] = o;
            }
        }
    }
}

// ======================================================================
// gk = log_sigmoid(KG1 @ Wkg2 + bkg2) / 16
// ======================================================================
__global__ void gk_kernel(const float* __restrict__ KG1,
                          const float* __restrict__ W2,
                          const float* __restrict__ b2,
                          float* __restrict__ GK)
{
    __shared__ float a[16];
    int m = blockIdx.x;
    if (threadIdx.x < 16) a[threadIdx.x] = KG1[(size_t)m * 16 + threadIdx.x];
    __syncthreads();
    for (int c = threadIdx.x; c < DHALF; c += 128) {
        float z = b2[c];
#pragma unroll
        for (int r = 0; r < 16; r++) z = fmaf(a[r], W2[(size_t)r * DHALF + c], z);
        float ls = (z >= 0.f) ? -log1pf(expf(-z)) : (z - log1pf(expf(z)));
        GK[(size_t)m * DHALF + c] = ls * INV_NORM_GK;
    }
}

// ======================================================================
// decay precompute
// ======================================================================
__global__ void prep_kernel(float* __restrict__ Q, float* __restrict__ Kx,
                            const float* __restrict__ GK,
                            float* __restrict__ KD, float* __restrict__ DEC)
{
    int g = blockIdx.x * blockDim.x + threadIdx.x;
    int col = g & (DHALF - 1);
    int bc  = g >> 10;
    int row0 = ((bc >> 4) * TT) + ((bc & 15) * CHUNK);
    size_t base = (size_t)row0 * DHALF + col;

    float gs = 0.f;
#pragma unroll 4
    for (int i = 0; i < CHUNK; i++) gs += GK[base + (size_t)i * DHALF];

    float gc = 0.f;
    for (int i = 0; i < CHUNK; i++) {
        size_t idx = base + (size_t)i * DHALF;
        gc += GK[idx];
        Q[idx] *= expf(gc);
        float kv = Kx[idx];
        KD[idx] = kv * expf(gs - gc);
        Kx[idx] = kv * expf(-gc);
    }
    DEC[(size_t)bc * DHALF + col] = expf(gs);
}

// ======================================================================
// GLA main (fp32, unchanged)
// ======================================================================
__global__ __launch_bounds__(256, 1)
void gla_kernel(const float* __restrict__ Q, const float* __restrict__ Kx,
                const float* __restrict__ KD, const float* __restrict__ V,
                const float* __restrict__ DEC, float* __restrict__ O)
{
    extern __shared__ float sm[];
    float* qdt = sm;
    float* At  = sm + 128 * 128;
    float* S   = sm + 2 * 128 * 128;
    float* vs  = sm + 2 * 128 * 128 + 128 * 64;
    float* kt  = vs;
    __shared__ float dec[128];

    const int tid = threadIdx.x;
    const int tx = tid & 15, ty = tid >> 4;
    const int bb = blockIdx.z, h = blockIdx.y, vsl = blockIdx.x;
    const int colQ = h * DK;
    const int colV = h * DV + vsl * 64;

    for (int i = tid; i < 128 * 64; i += 256) S[i] = 0.f;

    for (int ch = 0; ch < NCH; ch++) {
        const int m0 = bb * TT + ch * CHUNK;
        __syncthreads();

        for (int idx = tid; idx < 128 * 32; idx += 256) {
            int r = idx >> 5, c4 = (idx & 31) << 2;
            float4 f = *(const float4*)&Q[(size_t)(m0 + r) * DHALF + colQ + c4];
            qdt[(c4 + 0) * 128 + r] = f.x; qdt[(c4 + 1) * 128 + r] = f.y;
            qdt[(c4 + 2) * 128 + r] = f.z; qdt[(c4 + 3) * 128 + r] = f.w;
        }

        float acc[8][8];
#pragma unroll
        for (int r = 0; r < 8; r++)
#pragma unroll
            for (int c = 0; c < 8; c++) acc[r][c] = 0.f;

        for (int dt = 0; dt < 8; dt++) {
            __syncthreads();
            for (int idx = tid; idx < 128 * 4; idx += 256) {
                int j = idx >> 2, c4 = (idx & 3) << 2;
                float4 f = *(const float4*)&Kx[(size_t)(m0 + j) * DHALF + colQ + dt * 16 + c4];
                kt[(c4 + 0) * 128 + j] = f.x; kt[(c4 + 1) * 128 + j] = f.y;
                kt[(c4 + 2) * 128 + j] = f.z; kt[(c4 + 3) * 128 + j] = f.w;
            }
            __syncthreads();
#pragma unroll
            for (int dl = 0; dl < 16; dl++) {
                int d = dt * 16 + dl;
                float a[8], b[8];
                float4 a0 = *(float4*)&qdt[d * 128 + ty * 8];
                float4 a1 = *(float4*)&qdt[d * 128 + ty * 8 + 4];
                float4 b0 = *(float4*)&kt[dl * 128 + tx * 8];
                float4 b1 = *(float4*)&kt[dl * 128 + tx * 8 + 4];
                a[0]=a0.x;a[1]=a0.y;a[2]=a0.z;a[3]=a0.w;
                a[4]=a1.x;a[5]=a1.y;a[6]=a1.z;a[7]=a1.w;
                b[0]=b0.x;b[1]=b0.y;b[2]=b0.z;b[3]=b0.w;
                b[4]=b1.x;b[5]=b1.y;b[6]=b1.z;b[7]=b1.w;
#pragma unroll
                for (int r = 0; r < 8; r++)
#pragma unroll
                    for (int c = 0; c < 8; c++)
                        acc[r][c] = fmaf(a[r], b[c], acc[r][c]);
            }
        }
#pragma unroll
        for (int r = 0; r < 8; r++) {
            int i = ty * 8 + r;
#pragma unroll
            for (int c = 0; c < 8; c++) {
                int j = tx * 8 + c;
                At[j * 128 + i] = (j <= i) ? acc[r][c] : 0.f;
            }
        }
        __syncthreads();

        for (int idx = tid; idx < 128 * 16; idx += 256) {
            int j = idx >> 4, c4 = (idx & 15) << 2;
            *(float4*)&vs[j * 64 + c4] =
                *(const float4*)&V[(size_t)(m0 + j) * DD + colV + c4];
        }
        __syncthreads();

        float oa[8][4];
#pragma unroll
        for (int r = 0; r < 8; r++)
#pragma unroll
            for (int c = 0; c < 4; c++) oa[r][c] = 0.f;

        for (int j = 0; j < 128; j++) {
            float a[8];
            float4 a0 = *(float4*)&At[j * 128 + ty * 8];
            float4 a1 = *(float4*)&At[j * 128 + ty * 8 + 4];
            float4 b  = *(float4*)&vs[j * 64 + tx * 4];
            a[0]=a0.x;a[1]=a0.y;a[2]=a0.z;a[3]=a0.w;
            a[4]=a1.x;a[5]=a1.y;a[6]=a1.z;a[7]=a1.w;
#pragma unroll
            for (int r = 0; r < 8; r++) {
                oa[r][0] = fmaf(a[r], b.x, oa[r][0]);
                oa[r][1] = fmaf(a[r], b.y, oa[r][1]);
                oa[r][2] = fmaf(a[r], b.z, oa[r][2]);
                oa[r][3] = fmaf(a[r], b.w, oa[r][3]);
            }
        }
        for (int d = 0; d < 128; d++) {
            float a[8];
            float4 a0 = *(float4*)&qdt[d * 128 + ty * 8];
            float4 a1 = *(float4*)&qdt[d * 128 + ty * 8 + 4];
            float4 b  = *(float4*)&S[d * 64 + tx * 4];
            a[0]=a0.x;a[1]=a0.y;a[2]=a0.z;a[3]=a0.w;
            a[4]=a1.x;a[5]=a1.y;a[6]=a1.z;a[7]=a1.w;
#pragma unroll
            for (int r = 0; r < 8; r++) {
                oa[r][0] = fmaf(a[r], b.x, oa[r][0]);
                oa[r][1] = fmaf(a[r], b.y, oa[r][1]);
                oa[r][2] = fmaf(a[r], b.z, oa[r][2]);
                oa[r][3] = fmaf(a[r], b.w, oa[r][3]);
            }
        }
#pragma unroll
        for (int r = 0; r < 8; r++) {
            int row = m0 + ty * 8 + r;
            float4 o; o.x = oa[r][0]; o.y = oa[r][1]; o.z = oa[r][2]; o.w = oa[r][3];
            *(float4*)&O[(size_t)row * DD + colV + tx * 4] = o;
        }
        __syncthreads();

        for (int idx = tid; idx < 128 * 32; idx += 256) {
            int j = idx >> 5, c4 = (idx & 31) << 2;
            *(float4*)&At[j * 128 + c4] =
                *(const float4*)&KD[(size_t)(m0 + j) * DHALF + colQ + c4];
        }
        if (tid < 128) dec[tid] = DEC[(size_t)(bb * NCH + ch) * DHALF + colQ + tid];
        __syncthreads();

        float sa[8][4];
#pragma unroll
        for (int r = 0; r < 8; r++) {
            int d = ty * 8 + r;
            float dv = dec[d];
#pragma unroll
            for (int c = 0; c < 4; c++)
                sa[r][c] = dv * S[d * 64 + tx * 4 + c];
        }
        for (int j = 0; j < 128; j++) {
            float a[8];
            float4 a0 = *(float4*)&At[j * 128 + ty * 8];
            float4 a1 = *(float4*)&At[j * 128 + ty * 8 + 4];
            float4 b  = *(float4*)&vs[j * 64 + tx * 4];
            a[0]=a0.x;a[1]=a0.y;a[2]=a0.z;a[3]=a0.w;
            a[4]=a1.x;a[5]=a1.y;a[6]=a1.z;a[7]=a1.w;
#pragma unroll
            for (int r = 0; r < 8; r++) {
                sa[r][0] = fmaf(a[r], b.x, sa[r][0]);
                sa[r][1] = fmaf(a[r], b.y, sa[r][1]);
                sa[r][2] = fmaf(a[r], b.z, sa[r][2]);
                sa[r][3] = fmaf(a[r], b.w, sa[r][3]);
            }
        }
#pragma unroll
        for (int r = 0; r < 8; r++) {
            int d = ty * 8 + r;
            float4 o; o.x = sa[r][0]; o.y = sa[r][1]; o.z = sa[r][2]; o.w = sa[r][3];
            *(float4*)&S[d * 64 + tx * 4] = o;
        }
    }
}

// ======================================================================
// GroupNorm(256) * silu(g) -> bf16 hi/lo split
// ======================================================================
__global__ void norm_gate_kernel(const float* __restrict__ O,
                                 const float* __restrict__ G,
                                 __nv_bfloat16* __restrict__ PH,
                                 __nv_bfloat16* __restrict__ PL)
{
    int m = blockIdx.x, h = blockIdx.y;
    int tid = threadIdx.x;
    size_t idx = (size_t)m * DD + h * DV + tid;
    float v = O[idx];
    float s = v, s2 = v * v;
#pragma unroll
    for (int off = 16; off; off >>= 1) {
        s  += __shfl_xor_sync(0xFFFFFFFFu, s,  off);
        s2 += __shfl_xor_sync(0xFFFFFFFFu, s2, off);
    }
    __shared__ float ws[8], ws2[8];
    int w = tid >> 5, l = tid & 31;
    if (l == 0) { ws[w] = s; ws2[w] = s2; }
    __syncthreads();
    float ts = 0.f, ts2 = 0.f;
#pragma unroll
    for (int i = 0; i < 8; i++) { ts += ws[i]; ts2 += ws2[i]; }
    float mu = ts * (1.f / 256.f);
    float var = ts2 * (1.f / 256.f) - mu * mu;
    float nv = (v - mu) * rsqrtf(var + 1e-5f);
    float gt = G[idx];
    float sg = gt / (1.f + expf(-gt));
    float val = sg * nv;
    __nv_bfloat16 hh = __float2bfloat16(val);
    PH[idx] = hh;
    PL[idx] = __float2bfloat16(val - __bfloat162float(hh));
}

// ======================================================================
extern "C" void kernel_launch(void* const* d_in, const int* in_sizes, int n_in,
                              void* d_out, int out_size)
{
    const float* x    = (const float*)d_in[0];
    const float* Wq   = (const float*)d_in[1];
    const float* Wk   = (const float*)d_in[2];
    const float* Wkg1 = (const float*)d_in[3];
    const float* Wkg2 = (const float*)d_in[4];
    const float* bkg2 = (const float*)d_in[5];
    const float* Wv   = (const float*)d_in[6];
    const float* Wg   = (const float*)d_in[7];
    const float* bg   = (const float*)d_in[8];
    const float* Wo   = (const float*)d_in[9];
    float* out = (float*)d_out;

    float *pQ, *pK, *pGK, *pKD, *pKG1, *pDEC, *pV, *pG, *pO;
    __nv_bfloat16 *pXH, *pXL, *pWTH, *pWTL, *pPH, *pPL;
    cudaGetSymbolAddress((void**)&pQ,   g_Q);
    cudaGetSymbolAddress((void**)&pK,   g_K);
    cudaGetSymbolAddress((void**)&pGK,  g_GK);
    cudaGetSymbolAddress((void**)&pKD,  g_KD);
    cudaGetSymbolAddress((void**)&pKG1, g_KG1);
    cudaGetSymbolAddress((void**)&pDEC, g_DEC);
    cudaGetSymbolAddress((void**)&pV,   g_V);
    cudaGetSymbolAddress((void**)&pG,   g_G);
    cudaGetSymbolAddress((void**)&pO,   g_O);
    cudaGetSymbolAddress((void**)&pXH,  g_XH);
    cudaGetSymbolAddress((void**)&pXL,  g_XL);
    cudaGetSymbolAddress((void**)&pWTH, g_WTH);
    cudaGetSymbolAddress((void**)&pWTL, g_WTL);
    cudaGetSymbolAddress((void**)&pPH,  g_PH);
    cudaGetSymbolAddress((void**)&pPL,  g_PL);

    cudaFuncSetAttribute(gla_kernel,
                         cudaFuncAttributeMaxDynamicSharedMemorySize, 196608);
    cudaFuncSetAttribute(gemm_mma,
                         cudaFuncAttributeMaxDynamicSharedMemorySize, 65536);

    const int GSM = 65536;
    dim3 tb(32, 8);

    // split x
    int n4 = MROWS * DD / 4;
    xsplit<<<(n4 + 255) / 256, 256>>>((const float4*)x, pXH, pXL, n4);

    // tiny fp32 GEMM for gk bottleneck
    sgemm128<<<dim3(1, MROWS / 128), 256>>>(x, Wkg1, pKG1, MROWS, 16, DD, 1.0f, nullptr);

    // Q projection
    wsplit_t<<<dim3(DHALF / 32, DD / 32), tb>>>(Wq, pWTH, pWTL, DD, DHALF);
    gemm_mma<<<dim3(DHALF / 128, MROWS / 128), 256, GSM>>>(pXH, pXL, pWTH, pWTL,
                                                           pQ, MROWS, DHALF, DD, 1.0f, nullptr);
    // K projection (scaled)
    wsplit_t<<<dim3(DHALF / 32, DD / 32), tb>>>(Wk, pWTH, pWTL, DD, DHALF);
    gemm_mma<<<dim3(DHALF / 128, MROWS / 128), 256, GSM>>>(pXH, pXL, pWTH, pWTL,
                                                           pK, MROWS, DHALF, DD, SCALING, nullptr);
    // V projection
    wsplit_t<<<dim3(DD / 32, DD / 32), tb>>>(Wv, pWTH, pWTL, DD, DD);
    gemm_mma<<<dim3(DD / 128, MROWS / 128), 256, GSM>>>(pXH, pXL, pWTH, pWTL,
                                                        pV, MROWS, DD, DD, 1.0f, nullptr);
    // G projection (+bias)
    wsplit_t<<<dim3(DD / 32, DD / 32), tb>>>(Wg, pWTH, pWTL, DD, DD);
    gemm_mma<<<dim3(DD / 128, MROWS / 128), 256, GSM>>>(pXH, pXL, pWTH, pWTL,
                                                        pG, MROWS, DD, DD, 1.0f, bg);

    // gk + decay precompute
    gk_kernel<<<MROWS, 128>>>(pKG1, Wkg2, bkg2, pGK);
    prep_kernel<<<256, 256>>>(pQ, pK, pGK, pKD, pDEC);

    // chunked GLA
    gla_kernel<<<dim3(DV / 64, HH, BB), 256, 196608>>>(pQ, pK, pKD, pV, pDEC, pO);

    // groupnorm + silu gate -> bf16 split
    norm_gate_kernel<<<dim3(MROWS, HH), 256>>>(pO, pG, pPH, pPL);

    // output projection
    wsplit_t<<<dim3(DD / 32, DD / 32), tb>>>(Wo, pWTH, pWTL, DD, DD);
    gemm_mma<<<dim3(DD / 128, MROWS / 128), 256, GSM>>>(pPH, pPL, pWTH, pWTL,
                                                        out, MROWS, DD, DD, 1.0f, nullptr);
}

// round 4
// speedup vs baseline: 2.7682x; 1.2664x over previous
#include <cuda_runtime.h>
#include <cuda_bf16.h>
#include <math.h>
#include <stdint.h>

// ---------------- problem constants ----------------
#define BB     4
#define TT     2048
#define DD     2048
#define HH     8
#define DK     128
#define DV     256
#define CHUNK  128
#define NCH    16
#define MROWS  (BB*TT)      // 8192
#define DHALF  (DD/2)       // 1024
#define SCALING 0.0625f
#define INV_NORM_GK (1.0f/16.0f)
#define NCHUNKS (BB*NCH*HH) // 512

// ---------------- scratch ----------------
__device__ float g_Q  [(size_t)MROWS * DHALF];
__device__ float g_K  [(size_t)MROWS * DHALF];
__device__ float g_GK [(size_t)MROWS * DHALF];
__device__ float g_KG1[(size_t)MROWS * 16];
__device__ float g_DEC[(size_t)BB * NCH * DHALF];
__device__ float g_V  [(size_t)MROWS * DD];
__device__ float g_G  [(size_t)MROWS * DD];
__device__ float g_O  [(size_t)MROWS * DD];
__device__ __nv_bfloat16 g_XH [(size_t)MROWS * DD];
__device__ __nv_bfloat16 g_XL [(size_t)MROWS * DD];
__device__ __nv_bfloat16 g_WTH[(size_t)DD * DD];
__device__ __nv_bfloat16 g_WTL[(size_t)DD * DD];
__device__ __nv_bfloat16 g_PH [(size_t)MROWS * DD];
__device__ __nv_bfloat16 g_PL [(size_t)MROWS * DD];
__device__ __nv_bfloat16 g_QH [(size_t)MROWS * DHALF];
__device__ __nv_bfloat16 g_QL [(size_t)MROWS * DHALF];
__device__ __nv_bfloat16 g_KH [(size_t)MROWS * DHALF];
__device__ __nv_bfloat16 g_KL [(size_t)MROWS * DHALF];
__device__ __nv_bfloat16 g_KDH[(size_t)MROWS * DHALF];
__device__ __nv_bfloat16 g_KDL[(size_t)MROWS * DHALF];
__device__ __nv_bfloat16 g_VH [(size_t)MROWS * DD];
__device__ __nv_bfloat16 g_VL [(size_t)MROWS * DD];
__device__ __nv_bfloat16 g_AH [(size_t)NCHUNKS * CHUNK * CHUNK];
__device__ __nv_bfloat16 g_AL [(size_t)NCHUNKS * CHUNK * CHUNK];

// ================= helpers =================
__device__ __forceinline__ uint32_t smem_u32(const void* p) {
    uint32_t a;
    asm("{ .reg .u64 t; cvta.to.shared.u64 t, %1; cvt.u32.u64 %0, t; }" : "=r"(a) : "l"(p));
    return a;
}
__device__ __forceinline__ void cpasync16(uint32_t dst, const void* src) {
    asm volatile("cp.async.cg.shared.global [%0], [%1], 16;" :: "r"(dst), "l"(src) : "memory");
}
__device__ __forceinline__ void ldsm_x4(uint32_t* r, uint32_t addr) {
    asm volatile("ldmatrix.sync.aligned.m8n8.x4.shared.b16 {%0,%1,%2,%3}, [%4];"
                 : "=r"(r[0]), "=r"(r[1]), "=r"(r[2]), "=r"(r[3]) : "r"(addr));
}
__device__ __forceinline__ void mma16816(float* c, const uint32_t* a, const uint32_t* b) {
    asm volatile(
        "mma.sync.aligned.m16n8k16.row.col.f32.bf16.bf16.f32 "
        "{%0,%1,%2,%3}, {%4,%5,%6,%7}, {%8,%9}, {%0,%1,%2,%3};"
        : "+f"(c[0]), "+f"(c[1]), "+f"(c[2]), "+f"(c[3])
        : "r"(a[0]), "r"(a[1]), "r"(a[2]), "r"(a[3]), "r"(b[0]), "r"(b[1]));
}
static __device__ __forceinline__ uint32_t sw128(uint32_t o) { return o ^ ((o >> 3) & 0x70); }

// generic combo: acc[MF][4][4] += A_tile(128/64 rows x K=128) @ B_tile^T
// tiles stored as 2 K-subtiles (64 elems=128B rows, sw128) of strides abs_/bbs.
template<int MF>
__device__ __forceinline__ void mma_combo(float (*acc)[4][4], uint32_t Ab, uint32_t abs_,
                                          uint32_t Bb, uint32_t bbs, int mw, int nw, int lane)
{
#pragma unroll
    for (int kb = 0; kb < 2; kb++) {
#pragma unroll
        for (int ks = 0; ks < 4; ks++) {
            uint32_t af[MF][4];
#pragma unroll
            for (int mf = 0; mf < MF; mf++) {
                int row = mw + mf * 16 + (lane & 15);
                uint32_t bo = (uint32_t)(row << 7) + (uint32_t)(ks << 5) + ((lane >> 4) << 4);
                ldsm_x4(af[mf], Ab + kb * abs_ + sw128(bo));
            }
            uint32_t bfr[4][2];
#pragma unroll
            for (int half = 0; half < 2; half++) {
                int i2 = lane >> 3;
                int row = nw + half * 16 + ((i2 >> 1) << 3) + (lane & 7);
                uint32_t bo = (uint32_t)(row << 7) + (uint32_t)(ks << 5) + ((i2 & 1) << 4);
                uint32_t r[4];
                ldsm_x4(r, Bb + kb * bbs + sw128(bo));
                bfr[half * 2][0] = r[0];     bfr[half * 2][1] = r[1];
                bfr[half * 2 + 1][0] = r[2]; bfr[half * 2 + 1][1] = r[3];
            }
#pragma unroll
            for (int mf = 0; mf < MF; mf++)
#pragma unroll
                for (int nf = 0; nf < 4; nf++)
                    mma16816(acc[mf][nf], af[mf], bfr[nf]);
        }
    }
}

// ======================================================================
// bf16x3 emulated projection GEMM (verified R3): C = alpha*(A@B^T)+bias
// ======================================================================
__global__ __launch_bounds__(256, 2)
void gemm_mma(const __nv_bfloat16* __restrict__ Ahi, const __nv_bfloat16* __restrict__ Alo,
              const __nv_bfloat16* __restrict__ Bhi, const __nv_bfloat16* __restrict__ Blo,
              float* __restrict__ C, int M, int N, int K,
              float alpha, const float* __restrict__ bias)
{
    extern __shared__ char smem[];
    const uint32_t sbase = smem_u32(smem);
    const int tid = threadIdx.x;
    const int wid = tid >> 5, lane = tid & 31;
    const int m0 = blockIdx.y * 128;
    const int n0 = blockIdx.x * 128;
    const int mw = (wid & 1) * 64;
    const int nw = (wid >> 1) * 32;

    const int KC = K >> 6;
    const int TOT = 3 * KC;

    float acc[4][4][4];
#pragma unroll
    for (int i = 0; i < 4; i++)
#pragma unroll
        for (int j = 0; j < 4; j++)
#pragma unroll
            for (int l = 0; l < 4; l++) acc[i][j][l] = 0.f;

    const int lrow = tid >> 3;
    const int lch  = (tid & 7) << 4;
    const int lel  = (tid & 7) << 3;

    auto issue = [&](int it) {
        const int p = it / KC;
        const int k0 = (it - p * KC) << 6;
        const __nv_bfloat16* Ap = (p == 2) ? Alo : Ahi;
        const __nv_bfloat16* Bp = (p == 1) ? Blo : Bhi;
        const uint32_t sA = sbase + (uint32_t)(it & 1) * 32768u;
        const uint32_t sB = sA + 16384u;
#pragma unroll
        for (int l = 0; l < 4; l++) {
            int row = lrow + l * 32;
            uint32_t dst = sw128((uint32_t)(row << 7) + lch);
            cpasync16(sA + dst, Ap + (size_t)(m0 + row) * K + k0 + lel);
            cpasync16(sB + dst, Bp + (size_t)(n0 + row) * K + k0 + lel);
        }
        asm volatile("cp.async.commit_group;" ::: "memory");
    };

    issue(0);
    for (int it = 0; it < TOT; it++) {
        if (it + 1 < TOT) {
            issue(it + 1);
            asm volatile("cp.async.wait_group 1;" ::: "memory");
        } else {
            asm volatile("cp.async.wait_group 0;" ::: "memory");
        }
        __syncthreads();

        const uint32_t sA = sbase + (uint32_t)(it & 1) * 32768u;
        const uint32_t sB = sA + 16384u;
#pragma unroll
        for (int ks = 0; ks < 4; ks++) {
            uint32_t af[4][4], bf[4][2];
#pragma unroll
            for (int mf = 0; mf < 4; mf++) {
                int row = mw + mf * 16 + (lane & 15);
                uint32_t bo = (uint32_t)(row << 7) + (uint32_t)(ks << 5) + ((lane >> 4) << 4);
                ldsm_x4(af[mf], sA + sw128(bo));
            }
#pragma unroll
            for (int half = 0; half < 2; half++) {
                int i = lane >> 3;
                int row = nw + half * 16 + ((i >> 1) << 3) + (lane & 7);
                uint32_t bo = (uint32_t)(row << 7) + (uint32_t)(ks << 5) + ((i & 1) << 4);
                uint32_t r[4];
                ldsm_x4(r, sB + sw128(bo));
                bf[half * 2][0] = r[0];     bf[half * 2][1] = r[1];
                bf[half * 2 + 1][0] = r[2]; bf[half * 2 + 1][1] = r[3];
            }
#pragma unroll
            for (int mf = 0; mf < 4; mf++)
#pragma unroll
                for (int nf = 0; nf < 4; nf++)
                    mma16816(acc[mf][nf], af[mf], bf[nf]);
        }
        __syncthreads();
    }

    const int rb = m0 + mw + (lane >> 2);
    const int cb = n0 + nw + ((lane & 3) << 1);
#pragma unroll
    for (int mf = 0; mf < 4; mf++) {
#pragma unroll
        for (int half = 0; half < 2; half++) {
            int row = rb + mf * 16 + half * 8;
            float* cp = C + (size_t)row * N;
#pragma unroll
            for (int nf = 0; nf < 4; nf++) {
                int col = cb + nf * 8;
                float2 v;
                v.x = alpha * acc[mf][nf][half * 2 + 0];
                v.y = alpha * acc[mf][nf][half * 2 + 1];
                if (bias) { v.x += bias[col]; v.y += bias[col + 1]; }
                *(float2*)(cp + col) = v;
            }
        }
    }
}

// ======================================================================
// A-chunk kernel: per (b,ch,h) compute A = qd @ kexp^T (K=128), tril-mask,
// split to bf16 hi/lo, store to g_AH/g_AL [chunk][i][j].
// ======================================================================
__global__ __launch_bounds__(256, 1)
void akernel(const __nv_bfloat16* __restrict__ QH, const __nv_bfloat16* __restrict__ QL,
             const __nv_bfloat16* __restrict__ KH, const __nv_bfloat16* __restrict__ KL,
             __nv_bfloat16* __restrict__ AH, __nv_bfloat16* __restrict__ AL)
{
    extern __shared__ char smemc[];
    const uint32_t sb = smem_u32(smemc);
    const uint32_t oQH = 0, oQL = 32768, oKH = 65536, oKL = 98304;
    const int tid = threadIdx.x;
    const int wid = tid >> 5, lane = tid & 31;
    const int h = blockIdx.x, ch = blockIdx.y, bb = blockIdx.z;
    const int m0 = bb * TT + ch * CHUNK;
    const int colQ = h * 128;
    const size_t chA = (size_t)((bb * NCH + ch) * HH + h) * 16384;

    // load 4 tiles (qdh,qdl,kh,kl), each 128 rows x 256B (2 K-subtiles)
#pragma unroll
    for (int l = 0; l < 8; l++) {
        int idx = tid + (l << 8);
        int row = idx >> 4, u = idx & 15;
        int kb = u >> 3, sub = u & 7;
        uint32_t dst = (uint32_t)kb * 16384u + sw128((uint32_t)(row << 7) + (sub << 4));
        size_t so = (size_t)(m0 + row) * DHALF + colQ + kb * 64 + sub * 8;
        cpasync16(sb + oQH + dst, QH + so);
        cpasync16(sb + oQL + dst, QL + so);
        cpasync16(sb + oKH + dst, KH + so);
        cpasync16(sb + oKL + dst, KL + so);
    }
    asm volatile("cp.async.commit_group;" ::: "memory");
    asm volatile("cp.async.wait_group 0;" ::: "memory");
    __syncthreads();

    const int mw = (wid & 1) * 64, nw = (wid >> 1) * 32;
    float acc[4][4][4];
#pragma unroll
    for (int i = 0; i < 4; i++)
#pragma unroll
        for (int j = 0; j < 4; j++)
#pragma unroll
            for (int l = 0; l < 4; l++) acc[i][j][l] = 0.f;

    mma_combo<4>(acc, sb + oQH, 16384, sb + oKH, 16384, mw, nw, lane);
    mma_combo<4>(acc, sb + oQH, 16384, sb + oKL, 16384, mw, nw, lane);
    mma_combo<4>(acc, sb + oQL, 16384, sb + oKH, 16384, mw, nw, lane);

    // mask + split + store
#pragma unroll
    for (int mf = 0; mf < 4; mf++) {
#pragma unroll
        for (int half = 0; half < 2; half++) {
            int i = mw + mf * 16 + half * 8 + (lane >> 2);
#pragma unroll
            for (int nf = 0; nf < 4; nf++) {
                int j = nw + nf * 8 + ((lane & 3) << 1);
                float v0 = (j     <= i) ? acc[mf][nf][half * 2 + 0] : 0.f;
                float v1 = (j + 1 <= i) ? acc[mf][nf][half * 2 + 1] : 0.f;
                __nv_bfloat16 h0 = __float2bfloat16(v0);
                __nv_bfloat16 h1 = __float2bfloat16(v1);
                __nv_bfloat16 l0 = __float2bfloat16(v0 - __bfloat162float(h0));
                __nv_bfloat16 l1 = __float2bfloat16(v1 - __bfloat162float(h1));
                size_t oi = chA + (size_t)i * 128 + j;
                *(__nv_bfloat162*)(AH + oi) = __nv_bfloat162(h0, h1);
                *(__nv_bfloat162*)(AL + oi) = __nv_bfloat162(l0, l1);
            }
        }
    }
}

// ======================================================================
// gla2: tensor-core GLA recurrence. block per (b,h,dv64). S fp32 in smem.
// ======================================================================
__global__ __launch_bounds__(256, 1)
void gla2(const __nv_bfloat16* __restrict__ QH, const __nv_bfloat16* __restrict__ QL,
          const __nv_bfloat16* __restrict__ AH, const __nv_bfloat16* __restrict__ AL,
          const __nv_bfloat16* __restrict__ VH, const __nv_bfloat16* __restrict__ VL,
          const __nv_bfloat16* __restrict__ KDH, const __nv_bfloat16* __restrict__ KDL,
          const float* __restrict__ DEC, float* __restrict__ O)
{
    extern __shared__ char smemc[];
    const uint32_t sb = smem_u32(smemc);
    const uint32_t oQH = 0, oQL = 32768, oAT = 65536, oATl = 98304;
    const uint32_t oVH = 131072, oVL = 147456, oSH = 163840, oSL = 180224, oS32 = 196608;
    float* ST32 = (float*)(smemc + oS32);           // [n=64][d=128] fp32
    __shared__ float dec[128];

    const int tid = threadIdx.x;
    const int wid = tid >> 5, lane = tid & 31;
    const int vsl = blockIdx.x, h = blockIdx.y, bb = blockIdx.z;
    const int colQ = h * 128;
    const int colV = h * 256 + vsl * 64;
    const int mw = (wid & 3) * 32, nw = (wid >> 2) * 32;

    for (int i = tid; i < 8192; i += 256) ST32[i] = 0.f;

    for (int ch = 0; ch < NCH; ch++) {
        const int m0 = bb * TT + ch * CHUNK;
        const size_t chA = (size_t)((bb * NCH + ch) * HH + h) * 16384;
        __syncthreads();

        // qd + A tiles via cp.async
#pragma unroll
        for (int l = 0; l < 8; l++) {
            int idx = tid + (l << 8);
            int row = idx >> 4, u = idx & 15;
            int kb = u >> 3, sub = u & 7;
            uint32_t dst = (uint32_t)kb * 16384u + sw128((uint32_t)(row << 7) + (sub << 4));
            size_t so = (size_t)(m0 + row) * DHALF + colQ + kb * 64 + sub * 8;
            cpasync16(sb + oQH + dst, QH + so);
            cpasync16(sb + oQL + dst, QL + so);
            size_t sa = chA + (size_t)row * 128 + kb * 64 + sub * 8;
            cpasync16(sb + oAT  + dst, AH + sa);
            cpasync16(sb + oATl + dst, AL + sa);
        }
        asm volatile("cp.async.commit_group;" ::: "memory");

        // vT transpose: [j][n] -> [n][j]
#pragma unroll
        for (int l = 0; l < 16; l++) {
            int idx = tid + (l << 8);               // 0..4095
            int j = idx >> 5, n = (idx & 31) << 1;
            uint32_t wv = *(const uint32_t*)(VH + (size_t)(m0 + j) * DD + colV + n);
            uint32_t wl = *(const uint32_t*)(VL + (size_t)(m0 + j) * DD + colV + n);
            uint32_t kbo = (uint32_t)(j >> 6) * 8192u;
            uint32_t off0 = kbo + sw128((uint32_t)(n << 7) + ((j & 63) << 1));
            uint32_t off1 = kbo + sw128((uint32_t)((n + 1) << 7) + ((j & 63) << 1));
            *(unsigned short*)(smemc + oVH + off0) = (unsigned short)(wv & 0xffff);
            *(unsigned short*)(smemc + oVH + off1) = (unsigned short)(wv >> 16);
            *(unsigned short*)(smemc + oVL + off0) = (unsigned short)(wl & 0xffff);
            *(unsigned short*)(smemc + oVL + off1) = (unsigned short)(wl >> 16);
        }
        // ST regen from fp32 master
        for (int i = tid; i < 8192; i += 256) {
            int n = i >> 7, d = i & 127;
            float v = ST32[i];
            __nv_bfloat16 hv = __float2bfloat16(v);
            __nv_bfloat16 lv = __float2bfloat16(v - __bfloat162float(hv));
            uint32_t off = (uint32_t)(d >> 6) * 8192u + sw128((uint32_t)(n << 7) + ((d & 63) << 1));
            *(__nv_bfloat16*)(smemc + oSH + off) = hv;
            *(__nv_bfloat16*)(smemc + oSL + off) = lv;
        }
        if (tid < 128) dec[tid] = DEC[(size_t)(bb * NCH + ch) * DHALF + colQ + tid];
        asm volatile("cp.async.wait_group 0;" ::: "memory");
        __syncthreads();

        // ---- O phase: o = tril(A)@v + qd@S ----
        float acc[2][4][4];
#pragma unroll
        for (int i = 0; i < 2; i++)
#pragma unroll
            for (int j = 0; j < 4; j++)
#pragma unroll
                for (int l = 0; l < 4; l++) acc[i][j][l] = 0.f;

        mma_combo<2>(acc, sb + oAT,  16384, sb + oVH, 8192, mw, nw, lane);
        mma_combo<2>(acc, sb + oAT,  16384, sb + oVL, 8192, mw, nw, lane);
        mma_combo<2>(acc, sb + oATl, 16384, sb + oVH, 8192, mw, nw, lane);
        mma_combo<2>(acc, sb + oQH,  16384, sb + oSH, 8192, mw, nw, lane);
        mma_combo<2>(acc, sb + oQH,  16384, sb + oSL, 8192, mw, nw, lane);
        mma_combo<2>(acc, sb + oQL,  16384, sb + oSH, 8192, mw, nw, lane);

#pragma unroll
        for (int mf = 0; mf < 2; mf++) {
#pragma unroll
            for (int half = 0; half < 2; half++) {
                int row = m0 + mw + mf * 16 + half * 8 + (lane >> 2);
#pragma unroll
                for (int nf = 0; nf < 4; nf++) {
                    int col = colV + nw + nf * 8 + ((lane & 3) << 1);
                    float2 v;
                    v.x = acc[mf][nf][half * 2 + 0];
                    v.y = acc[mf][nf][half * 2 + 1];
                    *(float2*)&O[(size_t)row * DD + col] = v;
                }
            }
        }
        __syncthreads();   // A/qd tiles free

        // kdT transpose into the A region: [j][d] -> [d][j]
#pragma unroll
        for (int l = 0; l < 32; l++) {
            int idx = tid + (l << 8);               // 0..8191
            int j = idx >> 6, d = (idx & 63) << 1;
            uint32_t wv = *(const uint32_t*)(KDH + (size_t)(m0 + j) * DHALF + colQ + d);
            uint32_t wl = *(const uint32_t*)(KDL + (size_t)(m0 + j) * DHALF + colQ + d);
            uint32_t kbo = (uint32_t)(j >> 6) * 16384u;
            uint32_t off0 = kbo + sw128((uint32_t)(d << 7) + ((j & 63) << 1));
            uint32_t off1 = kbo + sw128((uint32_t)((d + 1) << 7) + ((j & 63) << 1));
            *(unsigned short*)(smemc + oAT  + off0) = (unsigned short)(wv & 0xffff);
            *(unsigned short*)(smemc + oAT  + off1) = (unsigned short)(wv >> 16);
            *(unsigned short*)(smemc + oATl + off0) = (unsigned short)(wl & 0xffff);
            *(unsigned short*)(smemc + oATl + off1) = (unsigned short)(wl >> 16);
        }
        __syncthreads();

        // ---- S phase: S = diag(dec) S + kd^T @ v ----
        float sacc[2][4][4];
#pragma unroll
        for (int i = 0; i < 2; i++)
#pragma unroll
            for (int j = 0; j < 4; j++)
#pragma unroll
                for (int l = 0; l < 4; l++) sacc[i][j][l] = 0.f;

        mma_combo<2>(sacc, sb + oAT,  16384, sb + oVH, 8192, mw, nw, lane);
        mma_combo<2>(sacc, sb + oAT,  16384, sb + oVL, 8192, mw, nw, lane);
        mma_combo<2>(sacc, sb + oATl, 16384, sb + oVH, 8192, mw, nw, lane);

#pragma unroll
        for (int mf = 0; mf < 2; mf++) {
#pragma unroll
            for (int half = 0; half < 2; half++) {
                int d = mw + mf * 16 + half * 8 + (lane >> 2);
                float dv = dec[d];
#pragma unroll
                for (int nf = 0; nf < 4; nf++) {
                    int n = nw + nf * 8 + ((lane & 3) << 1);
                    int i0 = n * 128 + d, i1 = (n + 1) * 128 + d;
                    ST32[i0] = dv * ST32[i0] + sacc[mf][nf][half * 2 + 0];
                    ST32[i1] = dv * ST32[i1] + sacc[mf][nf][half * 2 + 1];
                }
            }
        }
    }
}

// ======================================================================
// split fp32 array -> bf16 hi/lo (x and V)
// ======================================================================
__global__ void xsplit(const float4* __restrict__ X, __nv_bfloat16* __restrict__ H,
                       __nv_bfloat16* __restrict__ L, int n4)
{
    int i = blockIdx.x * blockDim.x + threadIdx.x;
    if (i >= n4) return;
    float4 v = X[i];
    __nv_bfloat16 h0 = __float2bfloat16(v.x), h1 = __float2bfloat16(v.y);
    __nv_bfloat16 h2 = __float2bfloat16(v.z), h3 = __float2bfloat16(v.w);
    __nv_bfloat16 l0 = __float2bfloat16(v.x - __bfloat162float(h0));
    __nv_bfloat16 l1 = __float2bfloat16(v.y - __bfloat162float(h1));
    __nv_bfloat16 l2 = __float2bfloat16(v.z - __bfloat162float(h2));
    __nv_bfloat16 l3 = __float2bfloat16(v.w - __bfloat162float(h3));
    __nv_bfloat162* Hp = (__nv_bfloat162*)H;
    __nv_bfloat162* Lp = (__nv_bfloat162*)L;
    Hp[i * 2]     = __nv_bfloat162(h0, h1);
    Hp[i * 2 + 1] = __nv_bfloat162(h2, h3);
    Lp[i * 2]     = __nv_bfloat162(l0, l1);
    Lp[i * 2 + 1] = __nv_bfloat162(l2, l3);
}

// ======================================================================
// transpose W [K,N] -> Th/Tl [N,K] bf16 split
// ======================================================================
__global__ void wsplit_t(const float* __restrict__ W, __nv_bfloat16* __restrict__ Th,
                         __nv_bfloat16* __restrict__ Tl, int K, int N)
{
    __shared__ float t[32][33];
    const int n0 = blockIdx.x * 32, k0 = blockIdx.y * 32;
    const int tx = threadIdx.x, ty = threadIdx.y;
#pragma unroll
    for (int i = 0; i < 4; i++) {
        int k = ty + i * 8;
        t[k][tx] = W[(size_t)(k0 + k) * N + n0 + tx];
    }
    __syncthreads();
#pragma unroll
    for (int i = 0; i < 4; i++) {
        int n = ty + i * 8;
        float v = t[tx][n];
        __nv_bfloat16 h = __float2bfloat16(v);
        size_t oi = (size_t)(n0 + n) * K + k0 + tx;
        Th[oi] = h;
        Tl[oi] = __float2bfloat16(v - __bfloat162float(h));
    }
}

// ======================================================================
// kg1: out[M,16] = x[M,2048] @ W1[2048,16]. warp per row.
// ======================================================================
__global__ void kg1_kernel(const float* __restrict__ x, const float* __restrict__ W1,
                           float* __restrict__ out)
{
    const int wid = threadIdx.x >> 5, lane = threadIdx.x & 31;
    const int row = blockIdx.x * 8 + wid;
    const float* xp = x + (size_t)row * DD;
    float acc[16];
#pragma unroll
    for (int c = 0; c < 16; c++) acc[c] = 0.f;
    for (int k = lane; k < DD; k += 32) {
        float xv = xp[k];
        const float4* wp = (const float4*)(W1 + (size_t)k * 16);
        float4 w0 = wp[0], w1 = wp[1], w2 = wp[2], w3 = wp[3];
        acc[0]  += xv * w0.x; acc[1]  += xv * w0.y; acc[2]  += xv * w0.z; acc[3]  += xv * w0.w;
        acc[4]  += xv * w1.x; acc[5]  += xv * w1.y; acc[6]  += xv * w1.z; acc[7]  += xv * w1.w;
        acc[8]  += xv * w2.x; acc[9]  += xv * w2.y; acc[10] += xv * w2.z; acc[11] += xv * w2.w;
        acc[12] += xv * w3.x; acc[13] += xv * w3.y; acc[14] += xv * w3.z; acc[15] += xv * w3.w;
    }
#pragma unroll
    for (int c = 0; c < 16; c++) {
        float v = acc[c];
#pragma unroll
        for (int off = 16; off; off >>= 1) v += __shfl_xor_sync(0xFFFFFFFFu, v, off);
        if (lane == 0) out[(size_t)row * 16 + c] = v;
    }
}

// ======================================================================
// gk = log_sigmoid(KG1 @ Wkg2 + bkg2) / 16
// ======================================================================
__global__ void gk_kernel(const float* __restrict__ KG1,
                          const float* __restrict__ W2,
                          const float* __restrict__ b2,
                          float* __restrict__ GK)
{
    __shared__ float a[16];
    int m = blockIdx.x;
    if (threadIdx.x < 16) a[threadIdx.x] = KG1[(size_t)m * 16 + threadIdx.x];
    __syncthreads();
    for (int c = threadIdx.x; c < DHALF; c += 128) {
        float z = b2[c];
#pragma unroll
        for (int r = 0; r < 16; r++) z = fmaf(a[r], W2[(size_t)r * DHALF + c], z);
        float ls = (z >= 0.f) ? -log1pf(expf(-z)) : (z - log1pf(expf(z)));
        GK[(size_t)m * DHALF + c] = ls * INV_NORM_GK;
    }
}

// ======================================================================
// decay precompute -> bf16 splits of qd, kexp, kd + DEC
// ======================================================================
__global__ void prep_kernel(const float* __restrict__ Q, const float* __restrict__ Kx,
                            const float* __restrict__ GK,
                            __nv_bfloat16* __restrict__ QHo, __nv_bfloat16* __restrict__ QLo,
                            __nv_bfloat16* __restrict__ KHo, __nv_bfloat16* __restrict__ KLo,
                            __nv_bfloat16* __restrict__ KDHo, __nv_bfloat16* __restrict__ KDLo,
                            float* __restrict__ DEC)
{
    int g = blockIdx.x * blockDim.x + threadIdx.x;
    int col = g & (DHALF - 1);
    int bc  = g >> 10;
    int row0 = ((bc >> 4) * TT) + ((bc & 15) * CHUNK);
    size_t base = (size_t)row0 * DHALF + col;

    float gs = 0.f;
#pragma unroll 4
    for (int i = 0; i < CHUNK; i++) gs += GK[base + (size_t)i * DHALF];

    float gc = 0.f;
    for (int i = 0; i < CHUNK; i++) {
        size_t idx = base + (size_t)i * DHALF;
        gc += GK[idx];
        float qd = Q[idx] * expf(gc);
        float kv = Kx[idx];
        float ke = kv * expf(-gc);
        float kd = kv * expf(gs - gc);
        __nv_bfloat16 qh = __float2bfloat16(qd);
        __nv_bfloat16 kh = __float2bfloat16(ke);
        __nv_bfloat16 dh = __float2bfloat16(kd);
        QHo[idx]  = qh; QLo[idx]  = __float2bfloat16(qd - __bfloat162float(qh));
        KHo[idx]  = kh; KLo[idx]  = __float2bfloat16(ke - __bfloat162float(kh));
        KDHo[idx] = dh; KDLo[idx] = __float2bfloat16(kd - __bfloat162float(dh));
    }
    DEC[(size_t)bc * DHALF + col] = expf(gs);
}

// ======================================================================
// GroupNorm(256) * silu(g) -> bf16 hi/lo split
// ======================================================================
__global__ void norm_gate_kernel(const float* __restrict__ O,
                                 const float* __restrict__ G,
                                 __nv_bfloat16* __restrict__ PH,
                                 __nv_bfloat16* __restrict__ PL)
{
    int m = blockIdx.x, h = blockIdx.y;
    int tid = threadIdx.x;
    size_t idx = (size_t)m * DD + h * DV + tid;
    float v = O[idx];
    float s = v, s2 = v * v;
#pragma unroll
    for (int off = 16; off; off >>= 1) {
        s  += __shfl_xor_sync(0xFFFFFFFFu, s,  off);
        s2 += __shfl_xor_sync(0xFFFFFFFFu, s2, off);
    }
    __shared__ float ws[8], ws2[8];
    int w = tid >> 5, l = tid & 31;
    if (l == 0) { ws[w] = s; ws2[w] = s2; }
    __syncthreads();
    float ts = 0.f, ts2 = 0.f;
#pragma unroll
    for (int i = 0; i < 8; i++) { ts += ws[i]; ts2 += ws2[i]; }
    float mu = ts * (1.f / 256.f);
    float var = ts2 * (1.f / 256.f) - mu * mu;
    float nv = (v - mu) * rsqrtf(var + 1e-5f);
    float gt = G[idx];
    float sg = gt / (1.f + expf(-gt));
    float val = sg * nv;
    __nv_bfloat16 hh = __float2bfloat16(val);
    PH[idx] = hh;
    PL[idx] = __float2bfloat16(val - __bfloat162float(hh));
}

// ======================================================================
extern "C" void kernel_launch(void* const* d_in, const int* in_sizes, int n_in,
                              void* d_out, int out_size)
{
    const float* x    = (const float*)d_in[0];
    const float* Wq   = (const float*)d_in[1];
    const float* Wk   = (const float*)d_in[2];
    const float* Wkg1 = (const float*)d_in[3];
    const float* Wkg2 = (const float*)d_in[4];
    const float* bkg2 = (const float*)d_in[5];
    const float* Wv   = (const float*)d_in[6];
    const float* Wg   = (const float*)d_in[7];
    const float* bg   = (const float*)d_in[8];
    const float* Wo   = (const float*)d_in[9];
    float* out = (float*)d_out;

    float *pQ, *pK, *pGK, *pKG1, *pDEC, *pV, *pG, *pO;
    __nv_bfloat16 *pXH, *pXL, *pWTH, *pWTL, *pPH, *pPL;
    __nv_bfloat16 *pQH, *pQL, *pKH, *pKL, *pKDH, *pKDL, *pVH, *pVL, *pAH, *pAL;
    cudaGetSymbolAddress((void**)&pQ,   g_Q);
    cudaGetSymbolAddress((void**)&pK,   g_K);
    cudaGetSymbolAddress((void**)&pGK,  g_GK);
    cudaGetSymbolAddress((void**)&pKG1, g_KG1);
    cudaGetSymbolAddress((void**)&pDEC, g_DEC);
    cudaGetSymbolAddress((void**)&pV,   g_V);
    cudaGetSymbolAddress((void**)&pG,   g_G);
    cudaGetSymbolAddress((void**)&pO,   g_O);
    cudaGetSymbolAddress((void**)&pXH,  g_XH);
    cudaGetSymbolAddress((void**)&pXL,  g_XL);
    cudaGetSymbolAddress((void**)&pWTH, g_WTH);
    cudaGetSymbolAddress((void**)&pWTL, g_WTL);
    cudaGetSymbolAddress((void**)&pPH,  g_PH);
    cudaGetSymbolAddress((void**)&pPL,  g_PL);
    cudaGetSymbolAddress((void**)&pQH,  g_QH);
    cudaGetSymbolAddress((void**)&pQL,  g_QL);
    cudaGetSymbolAddress((void**)&pKH,  g_KH);
    cudaGetSymbolAddress((void**)&pKL,  g_KL);
    cudaGetSymbolAddress((void**)&pKDH, g_KDH);
    cudaGetSymbolAddress((void**)&pKDL, g_KDL);
    cudaGetSymbolAddress((void**)&pVH,  g_VH);
    cudaGetSymbolAddress((void**)&pVL,  g_VL);
    cudaGetSymbolAddress((void**)&pAH,  g_AH);
    cudaGetSymbolAddress((void**)&pAL,  g_AL);

    cudaFuncSetAttribute(gemm_mma, cudaFuncAttributeMaxDynamicSharedMemorySize, 65536);
    cudaFuncSetAttribute(akernel,  cudaFuncAttributeMaxDynamicSharedMemorySize, 131072);
    cudaFuncSetAttribute(gla2,     cudaFuncAttributeMaxDynamicSharedMemorySize, 229376);

    const int GSM = 65536;
    dim3 tb(32, 8);

    // split x
    int n4 = MROWS * DD / 4;
    xsplit<<<(n4 + 255) / 256, 256>>>((const float4*)x, pXH, pXL, n4);

    // x @ Wkg1 (warp-per-row)
    kg1_kernel<<<MROWS / 8, 256>>>(x, Wkg1, pKG1);

    // Q projection
    wsplit_t<<<dim3(DHALF / 32, DD / 32), tb>>>(Wq, pWTH, pWTL, DD, DHALF);
    gemm_mma<<<dim3(DHALF / 128, MROWS / 128), 256, GSM>>>(pXH, pXL, pWTH, pWTL,
                                                           pQ, MROWS, DHALF, DD, 1.0f, nullptr);
    // K projection (scaled)
    wsplit_t<<<dim3(DHALF / 32, DD / 32), tb>>>(Wk, pWTH, pWTL, DD, DHALF);
    gemm_mma<<<dim3(DHALF / 128, MROWS / 128), 256, GSM>>>(pXH, pXL, pWTH, pWTL,
                                                           pK, MROWS, DHALF, DD, SCALING, nullptr);
    // gk + decay precompute -> bf16 splits
    gk_kernel<<<MROWS, 128>>>(pKG1, Wkg2, bkg2, pGK);
    prep_kernel<<<256, 256>>>(pQ, pK, pGK, pQH, pQL, pKH, pKL, pKDH, pKDL, pDEC);

    // A chunks (tensor)
    akernel<<<dim3(HH, NCH, BB), 256, 131072>>>(pQH, pQL, pKH, pKL, pAH, pAL);

    // V projection + split
    wsplit_t<<<dim3(DD / 32, DD / 32), tb>>>(Wv, pWTH, pWTL, DD, DD);
    gemm_mma<<<dim3(DD / 128, MROWS / 128), 256, GSM>>>(pXH, pXL, pWTH, pWTL,
                                                        pV, MROWS, DD, DD, 1.0f, nullptr);
    xsplit<<<(n4 + 255) / 256, 256>>>((const float4*)pV, pVH, pVL, n4);

    // G projection (+bias)
    wsplit_t<<<dim3(DD / 32, DD / 32), tb>>>(Wg, pWTH, pWTL, DD, DD);
    gemm_mma<<<dim3(DD / 128, MROWS / 128), 256, GSM>>>(pXH, pXL, pWTH, pWTL,
                                                        pG, MROWS, DD, DD, 1.0f, bg);

    // tensor GLA recurrence
    gla2<<<dim3(DV / 64, HH, BB), 256, 229376>>>(pQH, pQL, pAH, pAL, pVH, pVL,
                                                 pKDH, pKDL, pDEC, pO);

    // groupnorm + silu gate -> bf16 split
    norm_gate_kernel<<<dim3(MROWS, HH), 256>>>(pO, pG, pPH, pPL);

    // output projection
    wsplit_t<<<dim3(DD / 32, DD / 32), tb>>>(Wo, pWTH, pWTL, DD, DD);
    gemm_mma<<<dim3(DD / 128, MROWS / 128), 256, GSM>>>(pPH, pPL, pWTH, pWTL,
                                                        out, MROWS, DD, DD, 1.0f, nullptr);
}

// round 5
// speedup vs baseline: 2.8828x; 1.0414x over previous
#include <cuda_runtime.h>
#include <cuda_bf16.h>
#include <math.h>
#include <stdint.h>

// ---------------- problem constants ----------------
#define BB     4
#define TT     2048
#define DD     2048
#define HH     8
#define DK     128
#define DV     256
#define CHUNK  128
#define NCH    16
#define MROWS  (BB*TT)      // 8192
#define DHALF  (DD/2)       // 1024
#define SCALING 0.0625f
#define INV_NORM_GK (1.0f/16.0f)
#define NCHUNKS (BB*NCH*HH) // 512
#define NBLOBS  (BB*HH*4*NCH) // 2048 state blobs

// ---------------- scratch ----------------
__device__ float g_Q  [(size_t)MROWS * DHALF];
__device__ float g_K  [(size_t)MROWS * DHALF];
__device__ float g_GK [(size_t)MROWS * DHALF];
__device__ float g_KG1[(size_t)MROWS * 16];
__device__ float g_DEC[(size_t)BB * NCH * DHALF];
__device__ float g_G  [(size_t)MROWS * DD];
__device__ float g_O  [(size_t)MROWS * DD];
__device__ __nv_bfloat16 g_XH [(size_t)MROWS * DD];
__device__ __nv_bfloat16 g_XL [(size_t)MROWS * DD];
__device__ __nv_bfloat16 g_WTH[(size_t)DD * DD];
__device__ __nv_bfloat16 g_WTL[(size_t)DD * DD];
__device__ __nv_bfloat16 g_PH [(size_t)MROWS * DD];
__device__ __nv_bfloat16 g_PL [(size_t)MROWS * DD];
__device__ __nv_bfloat16 g_QH [(size_t)MROWS * DHALF];
__device__ __nv_bfloat16 g_QL [(size_t)MROWS * DHALF];
__device__ __nv_bfloat16 g_KH [(size_t)MROWS * DHALF];
__device__ __nv_bfloat16 g_KL [(size_t)MROWS * DHALF];
__device__ __nv_bfloat16 g_KDH[(size_t)MROWS * DHALF];
__device__ __nv_bfloat16 g_KDL[(size_t)MROWS * DHALF];
__device__ __nv_bfloat16 g_VH [(size_t)MROWS * DD];
__device__ __nv_bfloat16 g_VL [(size_t)MROWS * DD];
__device__ __nv_bfloat16 g_AH [(size_t)NCHUNKS * CHUNK * CHUNK];
__device__ __nv_bfloat16 g_AL [(size_t)NCHUNKS * CHUNK * CHUNK];
__device__ __nv_bfloat16 g_SBH[(size_t)NBLOBS * 64 * 128];
__device__ __nv_bfloat16 g_SBL[(size_t)NBLOBS * 64 * 128];

// ================= helpers =================
__device__ __forceinline__ uint32_t smem_u32(const void* p) {
    uint32_t a;
    asm("{ .reg .u64 t; cvta.to.shared.u64 t, %1; cvt.u32.u64 %0, t; }" : "=r"(a) : "l"(p));
    return a;
}
__device__ __forceinline__ void cpasync16(uint32_t dst, const void* src) {
    asm volatile("cp.async.cg.shared.global [%0], [%1], 16;" :: "r"(dst), "l"(src) : "memory");
}
__device__ __forceinline__ void ldsm_x4(uint32_t* r, uint32_t addr) {
    asm volatile("ldmatrix.sync.aligned.m8n8.x4.shared.b16 {%0,%1,%2,%3}, [%4];"
                 : "=r"(r[0]), "=r"(r[1]), "=r"(r[2]), "=r"(r[3]) : "r"(addr));
}
__device__ __forceinline__ void mma16816(float* c, const uint32_t* a, const uint32_t* b) {
    asm volatile(
        "mma.sync.aligned.m16n8k16.row.col.f32.bf16.bf16.f32 "
        "{%0,%1,%2,%3}, {%4,%5,%6,%7}, {%8,%9}, {%0,%1,%2,%3};"
        : "+f"(c[0]), "+f"(c[1]), "+f"(c[2]), "+f"(c[3])
        : "r"(a[0]), "r"(a[1]), "r"(a[2]), "r"(a[3]), "r"(b[0]), "r"(b[1]));
}
static __device__ __forceinline__ uint32_t sw128(uint32_t o) { return o ^ ((o >> 3) & 0x70); }

// acc[MF][4][4] += A_tile @ B_tile^T over K=128 (2 sw128 K-subtiles)
template<int MF>
__device__ __forceinline__ void mma_combo(float (*acc)[4][4], uint32_t Ab, uint32_t abs_,
                                          uint32_t Bb, uint32_t bbs, int mw, int nw, int lane)
{
#pragma unroll
    for (int kb = 0; kb < 2; kb++) {
#pragma unroll
        for (int ks = 0; ks < 4; ks++) {
            uint32_t af[MF][4];
#pragma unroll
            for (int mf = 0; mf < MF; mf++) {
                int row = mw + mf * 16 + (lane & 15);
                uint32_t bo = (uint32_t)(row << 7) + (uint32_t)(ks << 5) + ((lane >> 4) << 4);
                ldsm_x4(af[mf], Ab + kb * abs_ + sw128(bo));
            }
            uint32_t bfr[4][2];
#pragma unroll
            for (int half = 0; half < 2; half++) {
                int i2 = lane >> 3;
                int row = nw + half * 16 + ((i2 >> 1) << 3) + (lane & 7);
                uint32_t bo = (uint32_t)(row << 7) + (uint32_t)(ks << 5) + ((i2 & 1) << 4);
                uint32_t r[4];
                ldsm_x4(r, Bb + kb * bbs + sw128(bo));
                bfr[half * 2][0] = r[0];     bfr[half * 2][1] = r[1];
                bfr[half * 2 + 1][0] = r[2]; bfr[half * 2 + 1][1] = r[3];
            }
#pragma unroll
            for (int mf = 0; mf < MF; mf++)
#pragma unroll
                for (int nf = 0; nf < 4; nf++)
                    mma16816(acc[mf][nf], af[mf], bfr[nf]);
        }
    }
}

// ======================================================================
// gemm3: shared-fragment bf16x3 GEMM. Per 64-K chunk load AH/AL/BH/BL,
// do 3 combos (HH, HL, LH) with shared fragments. Tile 128x128.
// Optional fp32 output C and/or bf16 split output SHo/SLo.
// ======================================================================
__global__ __launch_bounds__(256, 1)
void gemm3(const __nv_bfloat16* __restrict__ AHp, const __nv_bfloat16* __restrict__ ALp,
           const __nv_bfloat16* __restrict__ BHp, const __nv_bfloat16* __restrict__ BLp,
           float* __restrict__ C, __nv_bfloat16* __restrict__ SHo, __nv_bfloat16* __restrict__ SLo,
           int M, int N, int K, float alpha, const float* __restrict__ bias)
{
    extern __shared__ char smem[];
    const uint32_t sbase = smem_u32(smem);
    const int tid = threadIdx.x;
    const int wid = tid >> 5, lane = tid & 31;
    const int m0 = blockIdx.y * 128, n0 = blockIdx.x * 128;
    const int mw = (wid & 1) * 64, nw = (wid >> 1) * 32;
    const int TOT = K >> 6;

    float acc[4][4][4];
#pragma unroll
    for (int i = 0; i < 4; i++)
#pragma unroll
        for (int j = 0; j < 4; j++)
#pragma unroll
            for (int l = 0; l < 4; l++) acc[i][j][l] = 0.f;

    auto issue = [&](int it) {
        const int k0 = it << 6;
        const uint32_t st = sbase + (uint32_t)(it & 1) * 65536u;
#pragma unroll
        for (int l = 0; l < 4; l++) {
            int c = tid + (l << 8);
            int row = c >> 3;
            uint32_t dst = sw128((uint32_t)(row << 7) + ((c & 7) << 4));
            int el = (c & 7) << 3;
            size_t ao = (size_t)(m0 + row) * K + k0 + el;
            size_t bo = (size_t)(n0 + row) * K + k0 + el;
            cpasync16(st + dst,         AHp + ao);
            cpasync16(st + 16384 + dst, ALp + ao);
            cpasync16(st + 32768 + dst, BHp + bo);
            cpasync16(st + 49152 + dst, BLp + bo);
        }
        asm volatile("cp.async.commit_group;" ::: "memory");
    };

    issue(0);
    for (int it = 0; it < TOT; it++) {
        if (it + 1 < TOT) {
            issue(it + 1);
            asm volatile("cp.async.wait_group 1;" ::: "memory");
        } else {
            asm volatile("cp.async.wait_group 0;" ::: "memory");
        }
        __syncthreads();
        const uint32_t st = sbase + (uint32_t)(it & 1) * 65536u;
#pragma unroll
        for (int ks = 0; ks < 4; ks++) {
            uint32_t afH[4][4], afL[4][4], bfH[4][2], bfL[4][2];
#pragma unroll
            for (int mf = 0; mf < 4; mf++) {
                int row = mw + mf * 16 + (lane & 15);
                uint32_t bo = (uint32_t)(row << 7) + (uint32_t)(ks << 5) + ((lane >> 4) << 4);
                uint32_t so = sw128(bo);
                ldsm_x4(afH[mf], st + so);
                ldsm_x4(afL[mf], st + 16384 + so);
            }
#pragma unroll
            for (int half = 0; half < 2; half++) {
                int i2 = lane >> 3;
                int row = nw + half * 16 + ((i2 >> 1) << 3) + (lane & 7);
                uint32_t bo = (uint32_t)(row << 7) + (uint32_t)(ks << 5) + ((i2 & 1) << 4);
                uint32_t so = sw128(bo);
                uint32_t r[4];
                ldsm_x4(r, st + 32768 + so);
                bfH[half * 2][0] = r[0];     bfH[half * 2][1] = r[1];
                bfH[half * 2 + 1][0] = r[2]; bfH[half * 2 + 1][1] = r[3];
                ldsm_x4(r, st + 49152 + so);
                bfL[half * 2][0] = r[0];     bfL[half * 2][1] = r[1];
                bfL[half * 2 + 1][0] = r[2]; bfL[half * 2 + 1][1] = r[3];
            }
#pragma unroll
            for (int mf = 0; mf < 4; mf++)
#pragma unroll
                for (int nf = 0; nf < 4; nf++) {
                    mma16816(acc[mf][nf], afH[mf], bfH[nf]);
                    mma16816(acc[mf][nf], afH[mf], bfL[nf]);
                    mma16816(acc[mf][nf], afL[mf], bfH[nf]);
                }
        }
        __syncthreads();
    }

    const int rb = m0 + mw + (lane >> 2);
    const int cb = n0 + nw + ((lane & 3) << 1);
#pragma unroll
    for (int mf = 0; mf < 4; mf++) {
#pragma unroll
        for (int half = 0; half < 2; half++) {
            int row = rb + mf * 16 + half * 8;
#pragma unroll
            for (int nf = 0; nf < 4; nf++) {
                int col = cb + nf * 8;
                float vx = alpha * acc[mf][nf][half * 2 + 0];
                float vy = alpha * acc[mf][nf][half * 2 + 1];
                if (bias) { vx += bias[col]; vy += bias[col + 1]; }
                if (C) {
                    float2 v; v.x = vx; v.y = vy;
                    *(float2*)(C + (size_t)row * N + col) = v;
                }
                if (SHo) {
                    __nv_bfloat16 h0 = __float2bfloat16(vx);
                    __nv_bfloat16 h1 = __float2bfloat16(vy);
                    __nv_bfloat16 l0 = __float2bfloat16(vx - __bfloat162float(h0));
                    __nv_bfloat16 l1 = __float2bfloat16(vy - __bfloat162float(h1));
                    *(__nv_bfloat162*)(SHo + (size_t)row * N + col) = __nv_bfloat162(h0, h1);
                    *(__nv_bfloat162*)(SLo + (size_t)row * N + col) = __nv_bfloat162(l0, l1);
                }
            }
        }
    }
}

// ======================================================================
// A-chunk kernel (verified R4): A = qd @ kexp^T, tril, split to bf16.
// ======================================================================
__global__ __launch_bounds__(256, 1)
void akernel(const __nv_bfloat16* __restrict__ QH, const __nv_bfloat16* __restrict__ QL,
             const __nv_bfloat16* __restrict__ KH, const __nv_bfloat16* __restrict__ KL,
             __nv_bfloat16* __restrict__ AH, __nv_bfloat16* __restrict__ AL)
{
    extern __shared__ char smemc[];
    const uint32_t sb = smem_u32(smemc);
    const uint32_t oQH = 0, oQL = 32768, oKH = 65536, oKL = 98304;
    const int tid = threadIdx.x;
    const int wid = tid >> 5, lane = tid & 31;
    const int h = blockIdx.x, ch = blockIdx.y, bb = blockIdx.z;
    const int m0 = bb * TT + ch * CHUNK;
    const int colQ = h * 128;
    const size_t chA = (size_t)((bb * NCH + ch) * HH + h) * 16384;

#pragma unroll
    for (int l = 0; l < 8; l++) {
        int idx = tid + (l << 8);
        int row = idx >> 4, u = idx & 15;
        int kb = u >> 3, sub = u & 7;
        uint32_t dst = (uint32_t)kb * 16384u + sw128((uint32_t)(row << 7) + (sub << 4));
        size_t so = (size_t)(m0 + row) * DHALF + colQ + kb * 64 + sub * 8;
        cpasync16(sb + oQH + dst, QH + so);
        cpasync16(sb + oQL + dst, QL + so);
        cpasync16(sb + oKH + dst, KH + so);
        cpasync16(sb + oKL + dst, KL + so);
    }
    asm volatile("cp.async.commit_group;" ::: "memory");
    asm volatile("cp.async.wait_group 0;" ::: "memory");
    __syncthreads();

    const int mw = (wid & 1) * 64, nw = (wid >> 1) * 32;
    float acc[4][4][4];
#pragma unroll
    for (int i = 0; i < 4; i++)
#pragma unroll
        for (int j = 0; j < 4; j++)
#pragma unroll
            for (int l = 0; l < 4; l++) acc[i][j][l] = 0.f;

    mma_combo<4>(acc, sb + oQH, 16384, sb + oKH, 16384, mw, nw, lane);
    mma_combo<4>(acc, sb + oQH, 16384, sb + oKL, 16384, mw, nw, lane);
    mma_combo<4>(acc, sb + oQL, 16384, sb + oKH, 16384, mw, nw, lane);

#pragma unroll
    for (int mf = 0; mf < 4; mf++) {
#pragma unroll
        for (int half = 0; half < 2; half++) {
            int i = mw + mf * 16 + half * 8 + (lane >> 2);
#pragma unroll
            for (int nf = 0; nf < 4; nf++) {
                int j = nw + nf * 8 + ((lane & 3) << 1);
                float v0 = (j     <= i) ? acc[mf][nf][half * 2 + 0] : 0.f;
                float v1 = (j + 1 <= i) ? acc[mf][nf][half * 2 + 1] : 0.f;
                __nv_bfloat16 h0 = __float2bfloat16(v0);
                __nv_bfloat16 h1 = __float2bfloat16(v1);
                __nv_bfloat16 l0 = __float2bfloat16(v0 - __bfloat162float(h0));
                __nv_bfloat16 l1 = __float2bfloat16(v1 - __bfloat162float(h1));
                size_t oi = chA + (size_t)i * 128 + j;
                *(__nv_bfloat162*)(AH + oi) = __nv_bfloat162(h0, h1);
                *(__nv_bfloat162*)(AL + oi) = __nv_bfloat162(l0, l1);
            }
        }
    }
}

// ======================================================================
// state_kernel: serial S recurrence per (b,h,dv64). Writes pre-update S^T
// blobs (bf16 split, sw128 tile layout) to global for o_kernel.
// ======================================================================
__global__ __launch_bounds__(256, 1)
void state_kernel(const __nv_bfloat16* __restrict__ KDH, const __nv_bfloat16* __restrict__ KDL,
                  const __nv_bfloat16* __restrict__ VH, const __nv_bfloat16* __restrict__ VL,
                  const float* __restrict__ DEC,
                  __nv_bfloat16* __restrict__ SBH, __nv_bfloat16* __restrict__ SBL)
{
    extern __shared__ char smemc[];
    const uint32_t sb = smem_u32(smemc);
    const uint32_t oKT = 0, oKTl = 32768, oVH = 65536, oVL = 81920;
    const uint32_t oSC = 98304, oSCl = 114688, oS32 = 131072;
    float* ST32 = (float*)(smemc + oS32);           // [n=64][d=128]
    __shared__ float dec[128];

    const int tid = threadIdx.x;
    const int wid = tid >> 5, lane = tid & 31;
    const int vsl = blockIdx.x, h = blockIdx.y, bb = blockIdx.z;
    const int colQ = h * 128;
    const int colV = h * 256 + vsl * 64;
    const int mw = (wid & 3) * 32, nw = (wid >> 2) * 32;
    const int blobbase = ((bb * HH + h) * 4 + vsl) * NCH;

    for (int i = tid; i < 8192; i += 256) ST32[i] = 0.f;

    for (int ch = 0; ch < NCH; ch++) {
        const int m0 = bb * TT + ch * CHUNK;
        __syncthreads();

        // kdT transpose: [j][d] -> [d][j]
#pragma unroll
        for (int l = 0; l < 32; l++) {
            int idx = tid + (l << 8);
            int j = idx >> 6, d = (idx & 63) << 1;
            uint32_t wv = *(const uint32_t*)(KDH + (size_t)(m0 + j) * DHALF + colQ + d);
            uint32_t wl = *(const uint32_t*)(KDL + (size_t)(m0 + j) * DHALF + colQ + d);
            uint32_t kbo = (uint32_t)(j >> 6) * 16384u;
            uint32_t off0 = kbo + sw128((uint32_t)(d << 7) + ((j & 63) << 1));
            uint32_t off1 = kbo + sw128((uint32_t)((d + 1) << 7) + ((j & 63) << 1));
            *(unsigned short*)(smemc + oKT  + off0) = (unsigned short)(wv & 0xffff);
            *(unsigned short*)(smemc + oKT  + off1) = (unsigned short)(wv >> 16);
            *(unsigned short*)(smemc + oKTl + off0) = (unsigned short)(wl & 0xffff);
            *(unsigned short*)(smemc + oKTl + off1) = (unsigned short)(wl >> 16);
        }
        // vT transpose: [j][n] -> [n][j]
#pragma unroll
        for (int l = 0; l < 16; l++) {
            int idx = tid + (l << 8);
            int j = idx >> 5, n = (idx & 31) << 1;
            uint32_t wv = *(const uint32_t*)(VH + (size_t)(m0 + j) * DD + colV + n);
            uint32_t wl = *(const uint32_t*)(VL + (size_t)(m0 + j) * DD + colV + n);
            uint32_t kbo = (uint32_t)(j >> 6) * 8192u;
            uint32_t off0 = kbo + sw128((uint32_t)(n << 7) + ((j & 63) << 1));
            uint32_t off1 = kbo + sw128((uint32_t)((n + 1) << 7) + ((j & 63) << 1));
            *(unsigned short*)(smemc + oVH + off0) = (unsigned short)(wv & 0xffff);
            *(unsigned short*)(smemc + oVH + off1) = (unsigned short)(wv >> 16);
            *(unsigned short*)(smemc + oVL + off0) = (unsigned short)(wl & 0xffff);
            *(unsigned short*)(smemc + oVL + off1) = (unsigned short)(wl >> 16);
        }
        // build S^T split scratch (pre-update state)
        for (int i = tid; i < 8192; i += 256) {
            int n = i >> 7, d = i & 127;
            float v = ST32[i];
            __nv_bfloat16 hv = __float2bfloat16(v);
            __nv_bfloat16 lv = __float2bfloat16(v - __bfloat162float(hv));
            uint32_t off = (uint32_t)(d >> 6) * 8192u + sw128((uint32_t)(n << 7) + ((d & 63) << 1));
            *(__nv_bfloat16*)(smemc + oSC  + off) = hv;
            *(__nv_bfloat16*)(smemc + oSCl + off) = lv;
        }
        if (tid < 128) dec[tid] = DEC[(size_t)(bb * NCH + ch) * DHALF + colQ + tid];
        __syncthreads();

        // coalesced blob copy-out
        {
            const float4* sH = (const float4*)(smemc + oSC);
            const float4* sL = (const float4*)(smemc + oSCl);
            float4* dH = (float4*)(SBH + (size_t)(blobbase + ch) * 8192);
            float4* dL = (float4*)(SBL + (size_t)(blobbase + ch) * 8192);
            for (int i = tid; i < 1024; i += 256) { dH[i] = sH[i]; dL[i] = sL[i]; }
        }

        // S phase: S += kd^T @ v (with decay)
        float sacc[2][4][4];
#pragma unroll
        for (int i = 0; i < 2; i++)
#pragma unroll
            for (int j = 0; j < 4; j++)
#pragma unroll
                for (int l = 0; l < 4; l++) sacc[i][j][l] = 0.f;

        mma_combo<2>(sacc, sb + oKT,  16384, sb + oVH, 8192, mw, nw, lane);
        mma_combo<2>(sacc, sb + oKT,  16384, sb + oVL, 8192, mw, nw, lane);
        mma_combo<2>(sacc, sb + oKTl, 16384, sb + oVH, 8192, mw, nw, lane);

#pragma unroll
        for (int mf = 0; mf < 2; mf++) {
#pragma unroll
            for (int half = 0; half < 2; half++) {
                int d = mw + mf * 16 + half * 8 + (lane >> 2);
                float dv = dec[d];
#pragma unroll
                for (int nf = 0; nf < 4; nf++) {
                    int n = nw + nf * 8 + ((lane & 3) << 1);
                    int i0 = n * 128 + d, i1 = (n + 1) * 128 + d;
                    ST32[i0] = dv * ST32[i0] + sacc[mf][nf][half * 2 + 0];
                    ST32[i1] = dv * ST32[i1] + sacc[mf][nf][half * 2 + 1];
                }
            }
        }
    }
}

// ======================================================================
// o_kernel: fully parallel O phase. block per (b,h,ch,dv64).
// o = tril(A)@v + qd@S_ch
// ======================================================================
__global__ __launch_bounds__(256, 1)
void o_kernel(const __nv_bfloat16* __restrict__ QH, const __nv_bfloat16* __restrict__ QL,
              const __nv_bfloat16* __restrict__ AH, const __nv_bfloat16* __restrict__ AL,
              const __nv_bfloat16* __restrict__ VH, const __nv_bfloat16* __restrict__ VL,
              const __nv_bfloat16* __restrict__ SBH, const __nv_bfloat16* __restrict__ SBL,
              float* __restrict__ O)
{
    extern __shared__ char smemc[];
    const uint32_t sb = smem_u32(smemc);
    const uint32_t oQH = 0, oQL = 32768, oAH = 65536, oAL = 98304;
    const uint32_t oVH = 131072, oVL = 147456, oSH = 163840, oSL = 180224;

    const int tid = threadIdx.x;
    const int wid = tid >> 5, lane = tid & 31;
    const int ch = blockIdx.x >> 2, vsl = blockIdx.x & 3;
    const int h = blockIdx.y, bb = blockIdx.z;
    const int m0 = bb * TT + ch * CHUNK;
    const int colQ = h * 128;
    const int colV = h * 256 + vsl * 64;
    const size_t chA = (size_t)((bb * NCH + ch) * HH + h) * 16384;
    const size_t blob = (size_t)(((bb * HH + h) * 4 + vsl) * NCH + ch) * 8192;
    const int mw = (wid & 3) * 32, nw = (wid >> 2) * 32;

    // qd + A tiles
#pragma unroll
    for (int l = 0; l < 8; l++) {
        int idx = tid + (l << 8);
        int row = idx >> 4, u = idx & 15;
        int kb = u >> 3, sub = u & 7;
        uint32_t dst = (uint32_t)kb * 16384u + sw128((uint32_t)(row << 7) + (sub << 4));
        size_t so = (size_t)(m0 + row) * DHALF + colQ + kb * 64 + sub * 8;
        cpasync16(sb + oQH + dst, QH + so);
        cpasync16(sb + oQL + dst, QL + so);
        size_t sa = chA + (size_t)row * 128 + kb * 64 + sub * 8;
        cpasync16(sb + oAH + dst, AH + sa);
        cpasync16(sb + oAL + dst, AL + sa);
    }
    // S blobs (already in tile layout)
#pragma unroll
    for (int l = 0; l < 4; l++) {
        int i = tid + (l << 8);
        cpasync16(sb + oSH + (i << 4), SBH + blob + (size_t)i * 8);
        cpasync16(sb + oSL + (i << 4), SBL + blob + (size_t)i * 8);
    }
    asm volatile("cp.async.commit_group;" ::: "memory");

    // vT transpose
#pragma unroll
    for (int l = 0; l < 16; l++) {
        int idx = tid + (l << 8);
        int j = idx >> 5, n = (idx & 31) << 1;
        uint32_t wv = *(const uint32_t*)(VH + (size_t)(m0 + j) * DD + colV + n);
        uint32_t wl = *(const uint32_t*)(VL + (size_t)(m0 + j) * DD + colV + n);
        uint32_t kbo = (uint32_t)(j >> 6) * 8192u;
        uint32_t off0 = kbo + sw128((uint32_t)(n << 7) + ((j & 63) << 1));
        uint32_t off1 = kbo + sw128((uint32_t)((n + 1) << 7) + ((j & 63) << 1));
        *(unsigned short*)(smemc + oVH + off0) = (unsigned short)(wv & 0xffff);
        *(unsigned short*)(smemc + oVH + off1) = (unsigned short)(wv >> 16);
        *(unsigned short*)(smemc + oVL + off0) = (unsigned short)(wl & 0xffff);
        *(unsigned short*)(smemc + oVL + off1) = (unsigned short)(wl >> 16);
    }
    asm volatile("cp.async.wait_group 0;" ::: "memory");
    __syncthreads();

    float acc[2][4][4];
#pragma unroll
    for (int i = 0; i < 2; i++)
#pragma unroll
        for (int j = 0; j < 4; j++)
#pragma unroll
            for (int l = 0; l < 4; l++) acc[i][j][l] = 0.f;

    mma_combo<2>(acc, sb + oAH, 16384, sb + oVH, 8192, mw, nw, lane);
    mma_combo<2>(acc, sb + oAH, 16384, sb + oVL, 8192, mw, nw, lane);
    mma_combo<2>(acc, sb + oAL, 16384, sb + oVH, 8192, mw, nw, lane);
    mma_combo<2>(acc, sb + oQH, 16384, sb + oSH, 8192, mw, nw, lane);
    mma_combo<2>(acc, sb + oQH, 16384, sb + oSL, 8192, mw, nw, lane);
    mma_combo<2>(acc, sb + oQL, 16384, sb + oSH, 8192, mw, nw, lane);

#pragma unroll
    for (int mf = 0; mf < 2; mf++) {
#pragma unroll
        for (int half = 0; half < 2; half++) {
            int row = m0 + mw + mf * 16 + half * 8 + (lane >> 2);
#pragma unroll
            for (int nf = 0; nf < 4; nf++) {
                int col = colV + nw + nf * 8 + ((lane & 3) << 1);
                float2 v;
                v.x = acc[mf][nf][half * 2 + 0];
                v.y = acc[mf][nf][half * 2 + 1];
                *(float2*)&O[(size_t)row * DD + col] = v;
            }
        }
    }
}

// ======================================================================
// split x -> bf16 hi/lo
// ======================================================================
__global__ void xsplit(const float4* __restrict__ X, __nv_bfloat16* __restrict__ H,
                       __nv_bfloat16* __restrict__ L, int n4)
{
    int i = blockIdx.x * blockDim.x + threadIdx.x;
    if (i >= n4) return;
    float4 v = X[i];
    __nv_bfloat16 h0 = __float2bfloat16(v.x), h1 = __float2bfloat16(v.y);
    __nv_bfloat16 h2 = __float2bfloat16(v.z), h3 = __float2bfloat16(v.w);
    __nv_bfloat16 l0 = __float2bfloat16(v.x - __bfloat162float(h0));
    __nv_bfloat16 l1 = __float2bfloat16(v.y - __bfloat162float(h1));
    __nv_bfloat16 l2 = __float2bfloat16(v.z - __bfloat162float(h2));
    __nv_bfloat16 l3 = __float2bfloat16(v.w - __bfloat162float(h3));
    __nv_bfloat162* Hp = (__nv_bfloat162*)H;
    __nv_bfloat162* Lp = (__nv_bfloat162*)L;
    Hp[i * 2]     = __nv_bfloat162(h0, h1);
    Hp[i * 2 + 1] = __nv_bfloat162(h2, h3);
    Lp[i * 2]     = __nv_bfloat162(l0, l1);
    Lp[i * 2 + 1] = __nv_bfloat162(l2, l3);
}

// ======================================================================
// transpose W [K,N] -> Th/Tl [N,K] bf16 split
// ======================================================================
__global__ void wsplit_t(const float* __restrict__ W, __nv_bfloat16* __restrict__ Th,
                         __nv_bfloat16* __restrict__ Tl, int K, int N)
{
    __shared__ float t[32][33];
    const int n0 = blockIdx.x * 32, k0 = blockIdx.y * 32;
    const int tx = threadIdx.x, ty = threadIdx.y;
#pragma unroll
    for (int i = 0; i < 4; i++) {
        int k = ty + i * 8;
        t[k][tx] = W[(size_t)(k0 + k) * N + n0 + tx];
    }
    __syncthreads();
#pragma unroll
    for (int i = 0; i < 4; i++) {
        int n = ty + i * 8;
        float v = t[tx][n];
        __nv_bfloat16 h = __float2bfloat16(v);
        size_t oi = (size_t)(n0 + n) * K + k0 + tx;
        Th[oi] = h;
        Tl[oi] = __float2bfloat16(v - __bfloat162float(h));
    }
}

// ======================================================================
// kg1: out[M,16] = x @ Wkg1. warp per row.
// ======================================================================
__global__ void kg1_kernel(const float* __restrict__ x, const float* __restrict__ W1,
                           float* __restrict__ out)
{
    const int wid = threadIdx.x >> 5, lane = threadIdx.x & 31;
    const int row = blockIdx.x * 8 + wid;
    const float* xp = x + (size_t)row * DD;
    float acc[16];
#pragma unroll
    for (int c = 0; c < 16; c++) acc[c] = 0.f;
    for (int k = lane; k < DD; k += 32) {
        float xv = xp[k];
        const float4* wp = (const float4*)(W1 + (size_t)k * 16);
        float4 w0 = wp[0], w1 = wp[1], w2 = wp[2], w3 = wp[3];
        acc[0]  += xv * w0.x; acc[1]  += xv * w0.y; acc[2]  += xv * w0.z; acc[3]  += xv * w0.w;
        acc[4]  += xv * w1.x; acc[5]  += xv * w1.y; acc[6]  += xv * w1.z; acc[7]  += xv * w1.w;
        acc[8]  += xv * w2.x; acc[9]  += xv * w2.y; acc[10] += xv * w2.z; acc[11] += xv * w2.w;
        acc[12] += xv * w3.x; acc[13] += xv * w3.y; acc[14] += xv * w3.z; acc[15] += xv * w3.w;
    }
#pragma unroll
    for (int c = 0; c < 16; c++) {
        float v = acc[c];
#pragma unroll
        for (int off = 16; off; off >>= 1) v += __shfl_xor_sync(0xFFFFFFFFu, v, off);
        if (lane == 0) out[(size_t)row * 16 + c] = v;
    }
}

// ======================================================================
// gk = log_sigmoid(KG1 @ Wkg2 + bkg2) / 16
// ======================================================================
__global__ void gk_kernel(const float* __restrict__ KG1,
                          const float* __restrict__ W2,
                          const float* __restrict__ b2,
                          float* __restrict__ GK)
{
    __shared__ float a[16];
    int m = blockIdx.x;
    if (threadIdx.x < 16) a[threadIdx.x] = KG1[(size_t)m * 16 + threadIdx.x];
    __syncthreads();
    for (int c = threadIdx.x; c < DHALF; c += 128) {
        float z = b2[c];
#pragma unroll
        for (int r = 0; r < 16; r++) z = fmaf(a[r], W2[(size_t)r * DHALF + c], z);
        float ls = (z >= 0.f) ? -log1pf(expf(-z)) : (z - log1pf(expf(z)));
        GK[(size_t)m * DHALF + c] = ls * INV_NORM_GK;
    }
}

// ======================================================================
// decay precompute -> bf16 splits of qd, kexp, kd + DEC
// ======================================================================
__global__ void prep_kernel(const float* __restrict__ Q, const float* __restrict__ Kx,
                            const float* __restrict__ GK,
                            __nv_bfloat16* __restrict__ QHo, __nv_bfloat16* __restrict__ QLo,
                            __nv_bfloat16* __restrict__ KHo, __nv_bfloat16* __restrict__ KLo,
                            __nv_bfloat16* __restrict__ KDHo, __nv_bfloat16* __restrict__ KDLo,
                            float* __restrict__ DEC)
{
    int g = blockIdx.x * blockDim.x + threadIdx.x;
    int col = g & (DHALF - 1);
    int bc  = g >> 10;
    int row0 = ((bc >> 4) * TT) + ((bc & 15) * CHUNK);
    size_t base = (size_t)row0 * DHALF + col;

    float gs = 0.f;
#pragma unroll 4
    for (int i = 0; i < CHUNK; i++) gs += GK[base + (size_t)i * DHALF];

    float gc = 0.f;
    for (int i = 0; i < CHUNK; i++) {
        size_t idx = base + (size_t)i * DHALF;
        gc += GK[idx];
        float qd = Q[idx] * expf(gc);
        float kv = Kx[idx];
        float ke = kv * expf(-gc);
        float kd = kv * expf(gs - gc);
        __nv_bfloat16 qh = __float2bfloat16(qd);
        __nv_bfloat16 kh = __float2bfloat16(ke);
        __nv_bfloat16 dh = __float2bfloat16(kd);
        QHo[idx]  = qh; QLo[idx]  = __float2bfloat16(qd - __bfloat162float(qh));
        KHo[idx]  = kh; KLo[idx]  = __float2bfloat16(ke - __bfloat162float(kh));
        KDHo[idx] = dh; KDLo[idx] = __float2bfloat16(kd - __bfloat162float(dh));
    }
    DEC[(size_t)bc * DHALF + col] = expf(gs);
}

// ======================================================================
// GroupNorm(256) * silu(g) -> bf16 hi/lo split
// ======================================================================
__global__ void norm_gate_kernel(const float* __restrict__ O,
                                 const float* __restrict__ G,
                                 __nv_bfloat16* __restrict__ PH,
                                 __nv_bfloat16* __restrict__ PL)
{
    int m = blockIdx.x, h = blockIdx.y;
    int tid = threadIdx.x;
    size_t idx = (size_t)m * DD + h * DV + tid;
    float v = O[idx];
    float s = v, s2 = v * v;
#pragma unroll
    for (int off = 16; off; off >>= 1) {
        s  += __shfl_xor_sync(0xFFFFFFFFu, s,  off);
        s2 += __shfl_xor_sync(0xFFFFFFFFu, s2, off);
    }
    __shared__ float ws[8], ws2[8];
    int w = tid >> 5, l = tid & 31;
    if (l == 0) { ws[w] = s; ws2[w] = s2; }
    __syncthreads();
    float ts = 0.f, ts2 = 0.f;
#pragma unroll
    for (int i = 0; i < 8; i++) { ts += ws[i]; ts2 += ws2[i]; }
    float mu = ts * (1.f / 256.f);
    float var = ts2 * (1.f / 256.f) - mu * mu;
    float nv = (v - mu) * rsqrtf(var + 1e-5f);
    float gt = G[idx];
    float sg = gt / (1.f + expf(-gt));
    float val = sg * nv;
    __nv_bfloat16 hh = __float2bfloat16(val);
    PH[idx] = hh;
    PL[idx] = __float2bfloat16(val - __bfloat162float(hh));
}

// ======================================================================
extern "C" void kernel_launch(void* const* d_in, const int* in_sizes, int n_in,
                              void* d_out, int out_size)
{
    const float* x    = (const float*)d_in[0];
    const float* Wq   = (const float*)d_in[1];
    const float* Wk   = (const float*)d_in[2];
    const float* Wkg1 = (const float*)d_in[3];
    const float* Wkg2 = (const float*)d_in[4];
    const float* bkg2 = (const float*)d_in[5];
    const float* Wv   = (const float*)d_in[6];
    const float* Wg   = (const float*)d_in[7];
    const float* bg   = (const float*)d_in[8];
    const float* Wo   = (const float*)d_in[9];
    float* out = (float*)d_out;

    float *pQ, *pK, *pGK, *pKG1, *pDEC, *pG, *pO;
    __nv_bfloat16 *pXH, *pXL, *pWTH, *pWTL, *pPH, *pPL;
    __nv_bfloat16 *pQH, *pQL, *pKH, *pKL, *pKDH, *pKDL, *pVH, *pVL, *pAH, *pAL, *pSBH, *pSBL;
    cudaGetSymbolAddress((void**)&pQ,   g_Q);
    cudaGetSymbolAddress((void**)&pK,   g_K);
    cudaGetSymbolAddress((void**)&pGK,  g_GK);
    cudaGetSymbolAddress((void**)&pKG1, g_KG1);
    cudaGetSymbolAddress((void**)&pDEC, g_DEC);
    cudaGetSymbolAddress((void**)&pG,   g_G);
    cudaGetSymbolAddress((void**)&pO,   g_O);
    cudaGetSymbolAddress((void**)&pXH,  g_XH);
    cudaGetSymbolAddress((void**)&pXL,  g_XL);
    cudaGetSymbolAddress((void**)&pWTH, g_WTH);
    cudaGetSymbolAddress((void**)&pWTL, g_WTL);
    cudaGetSymbolAddress((void**)&pPH,  g_PH);
    cudaGetSymbolAddress((void**)&pPL,  g_PL);
    cudaGetSymbolAddress((void**)&pQH,  g_QH);
    cudaGetSymbolAddress((void**)&pQL,  g_QL);
    cudaGetSymbolAddress((void**)&pKH,  g_KH);
    cudaGetSymbolAddress((void**)&pKL,  g_KL);
    cudaGetSymbolAddress((void**)&pKDH, g_KDH);
    cudaGetSymbolAddress((void**)&pKDL, g_KDL);
    cudaGetSymbolAddress((void**)&pVH,  g_VH);
    cudaGetSymbolAddress((void**)&pVL,  g_VL);
    cudaGetSymbolAddress((void**)&pAH,  g_AH);
    cudaGetSymbolAddress((void**)&pAL,  g_AL);
    cudaGetSymbolAddress((void**)&pSBH, g_SBH);
    cudaGetSymbolAddress((void**)&pSBL, g_SBL);

    cudaFuncSetAttribute(gemm3,        cudaFuncAttributeMaxDynamicSharedMemorySize, 131072);
    cudaFuncSetAttribute(akernel,      cudaFuncAttributeMaxDynamicSharedMemorySize, 131072);
    cudaFuncSetAttribute(state_kernel, cudaFuncAttributeMaxDynamicSharedMemorySize, 163840);
    cudaFuncSetAttribute(o_kernel,     cudaFuncAttributeMaxDynamicSharedMemorySize, 196608);

    dim3 tb(32, 8);
    int n4 = MROWS * DD / 4;

    // split x
    xsplit<<<(n4 + 255) / 256, 256>>>((const float4*)x, pXH, pXL, n4);
    // x @ Wkg1
    kg1_kernel<<<MROWS / 8, 256>>>(x, Wkg1, pKG1);

    // Q projection
    wsplit_t<<<dim3(DHALF / 32, DD / 32), tb>>>(Wq, pWTH, pWTL, DD, DHALF);
    gemm3<<<dim3(DHALF / 128, MROWS / 128), 256, 131072>>>(pXH, pXL, pWTH, pWTL,
        pQ, nullptr, nullptr, MROWS, DHALF, DD, 1.0f, nullptr);
    // K projection (scaled)
    wsplit_t<<<dim3(DHALF / 32, DD / 32), tb>>>(Wk, pWTH, pWTL, DD, DHALF);
    gemm3<<<dim3(DHALF / 128, MROWS / 128), 256, 131072>>>(pXH, pXL, pWTH, pWTL,
        pK, nullptr, nullptr, MROWS, DHALF, DD, SCALING, nullptr);

    // gk + decay precompute
    gk_kernel<<<MROWS, 128>>>(pKG1, Wkg2, bkg2, pGK);
    prep_kernel<<<256, 256>>>(pQ, pK, pGK, pQH, pQL, pKH, pKL, pKDH, pKDL, pDEC);

    // A chunks
    akernel<<<dim3(HH, NCH, BB), 256, 131072>>>(pQH, pQL, pKH, pKL, pAH, pAL);

    // V projection -> bf16 split directly (no fp32 V)
    wsplit_t<<<dim3(DD / 32, DD / 32), tb>>>(Wv, pWTH, pWTL, DD, DD);
    gemm3<<<dim3(DD / 128, MROWS / 128), 256, 131072>>>(pXH, pXL, pWTH, pWTL,
        nullptr, pVH, pVL, MROWS, DD, DD, 1.0f, nullptr);

    // serial state recurrence -> S blobs
    state_kernel<<<dim3(4, HH, BB), 256, 163840>>>(pKDH, pKDL, pVH, pVL, pDEC, pSBH, pSBL);

    // G projection (+bias)
    wsplit_t<<<dim3(DD / 32, DD / 32), tb>>>(Wg, pWTH, pWTL, DD, DD);
    gemm3<<<dim3(DD / 128, MROWS / 128), 256, 131072>>>(pXH, pXL, pWTH, pWTL,
        pG, nullptr, nullptr, MROWS, DD, DD, 1.0f, bg);

    // parallel O phase
    o_kernel<<<dim3(NCH * 4, HH, BB), 256, 196608>>>(pQH, pQL, pAH, pAL, pVH, pVL,
                                                     pSBH, pSBL, pO);

    // groupnorm + silu gate -> bf16 split
    norm_gate_kernel<<<dim3(MROWS, HH), 256>>>(pO, pG, pPH, pPL);

    // output projection
    wsplit_t<<<dim3(DD / 32, DD / 32), tb>>>(Wo, pWTH, pWTL, DD, DD);
    gemm3<<<dim3(DD / 128, MROWS / 128), 256, 131072>>>(pPH, pPL, pWTH, pWTL,
        out, nullptr, nullptr, MROWS, DD, DD, 1.0f, nullptr);
}

// round 7
// speedup vs baseline: 3.0962x; 1.0740x over previous
#include <cuda_runtime.h>
#include <cuda_bf16.h>
#include <math.h>
#include <stdint.h>

// ---------------- problem constants ----------------
#define BB     4
#define TT     2048
#define DD     2048
#define HH     8
#define DK     128
#define DV     256
#define CHUNK  128
#define NCH    16
#define MROWS  (BB*TT)      // 8192
#define DHALF  (DD/2)       // 1024
#define SCALING 0.0625f
#define INV_NORM_GK (1.0f/16.0f)
#define NCHUNKS (BB*NCH*HH) // 512
#define NBLOBS  (BB*HH*4*NCH) // 2048 state blobs
#define WTROWS 8192         // combined transposed weights: Q|K|V|G|O

// ---------------- scratch ----------------
__device__ float g_QK [(size_t)MROWS * 2048];
__device__ float g_GK [(size_t)MROWS * DHALF];
__device__ float g_KG1[(size_t)MROWS * 16];
__device__ float g_DEC[(size_t)BB * NCH * DHALF];
__device__ float g_G  [(size_t)MROWS * DD];
__device__ float g_O  [(size_t)MROWS * DD];
__device__ __nv_bfloat16 g_XH [(size_t)MROWS * DD];
__device__ __nv_bfloat16 g_XL [(size_t)MROWS * DD];
__device__ __nv_bfloat16 g_WTH[(size_t)WTROWS * DD];
__device__ __nv_bfloat16 g_WTL[(size_t)WTROWS * DD];
__device__ __nv_bfloat16 g_PH [(size_t)MROWS * DD];
__device__ __nv_bfloat16 g_PL [(size_t)MROWS * DD];
__device__ __nv_bfloat16 g_QH [(size_t)MROWS * DHALF];
__device__ __nv_bfloat16 g_QL [(size_t)MROWS * DHALF];
__device__ __nv_bfloat16 g_KH [(size_t)MROWS * DHALF];
__device__ __nv_bfloat16 g_KL [(size_t)MROWS * DHALF];
__device__ __nv_bfloat16 g_KDH[(size_t)MROWS * DHALF];
__device__ __nv_bfloat16 g_KDL[(size_t)MROWS * DHALF];
__device__ __nv_bfloat16 g_VH [(size_t)MROWS * DD];
__device__ __nv_bfloat16 g_VL [(size_t)MROWS * DD];
__device__ __nv_bfloat16 g_AH [(size_t)NCHUNKS * CHUNK * CHUNK];
__device__ __nv_bfloat16 g_AL [(size_t)NCHUNKS * CHUNK * CHUNK];
__device__ __nv_bfloat16 g_SBH[(size_t)NBLOBS * 64 * 128];
__device__ __nv_bfloat16 g_SBL[(size_t)NBLOBS * 64 * 128];

// ================= helpers =================
__device__ __forceinline__ uint32_t smem_u32(const void* p) {
    uint32_t a;
    asm("{ .reg .u64 t; cvta.to.shared.u64 t, %1; cvt.u32.u64 %0, t; }" : "=r"(a) : "l"(p));
    return a;
}
__device__ __forceinline__ void cpasync16(uint32_t dst, const void* src) {
    asm volatile("cp.async.cg.shared.global [%0], [%1], 16;" :: "r"(dst), "l"(src) : "memory");
}
__device__ __forceinline__ void ldsm_x4(uint32_t* r, uint32_t addr) {
    asm volatile("ldmatrix.sync.aligned.m8n8.x4.shared.b16 {%0,%1,%2,%3}, [%4];"
                 : "=r"(r[0]), "=r"(r[1]), "=r"(r[2]), "=r"(r[3]) : "r"(addr));
}
__device__ __forceinline__ void mma16816(float* c, const uint32_t* a, const uint32_t* b) {
    asm volatile(
        "mma.sync.aligned.m16n8k16.row.col.f32.bf16.bf16.f32 "
        "{%0,%1,%2,%3}, {%4,%5,%6,%7}, {%8,%9}, {%0,%1,%2,%3};"
        : "+f"(c[0]), "+f"(c[1]), "+f"(c[2]), "+f"(c[3])
        : "r"(a[0]), "r"(a[1]), "r"(a[2]), "r"(a[3]), "r"(b[0]), "r"(b[1]));
}
static __device__ __forceinline__ uint32_t sw128(uint32_t o) { return o ^ ((o >> 3) & 0x70); }

// acc[MF][4][4] += A_tile @ B_tile^T over K=128 (2 sw128 K-subtiles)
template<int MF>
__device__ __forceinline__ void mma_combo(float (*acc)[4][4], uint32_t Ab, uint32_t abs_,
                                          uint32_t Bb, uint32_t bbs, int mw, int nw, int lane)
{
#pragma unroll
    for (int kb = 0; kb < 2; kb++) {
#pragma unroll
        for (int ks = 0; ks < 4; ks++) {
            uint32_t af[MF][4];
#pragma unroll
            for (int mf = 0; mf < MF; mf++) {
                int row = mw + mf * 16 + (lane & 15);
                uint32_t bo = (uint32_t)(row << 7) + (uint32_t)(ks << 5) + ((lane >> 4) << 4);
                ldsm_x4(af[mf], Ab + kb * abs_ + sw128(bo));
            }
            uint32_t bfr[4][2];
#pragma unroll
            for (int half = 0; half < 2; half++) {
                int i2 = lane >> 3;
                int row = nw + half * 16 + ((i2 >> 1) << 3) + (lane & 7);
                uint32_t bo = (uint32_t)(row << 7) + (uint32_t)(ks << 5) + ((i2 & 1) << 4);
                uint32_t r[4];
                ldsm_x4(r, Bb + kb * bbs + sw128(bo));
                bfr[half * 2][0] = r[0];     bfr[half * 2][1] = r[1];
                bfr[half * 2 + 1][0] = r[2]; bfr[half * 2 + 1][1] = r[3];
            }
#pragma unroll
            for (int mf = 0; mf < MF; mf++)
#pragma unroll
                for (int nf = 0; nf < 4; nf++)
                    mma16816(acc[mf][nf], af[mf], bfr[nf]);
        }
    }
}

// ======================================================================
// gemm3: shared-fragment bf16x3 GEMM, 3-stage cp.async pipeline,
// ONE __syncthreads per K-chunk. Tile 128x128, K-chunk 64.
// Optional fp32 output C and/or bf16 split output SHo/SLo.
// ======================================================================
__global__ __launch_bounds__(256, 1)
void gemm3(const __nv_bfloat16* __restrict__ AHp, const __nv_bfloat16* __restrict__ ALp,
           const __nv_bfloat16* __restrict__ BHp, const __nv_bfloat16* __restrict__ BLp,
           float* __restrict__ C, __nv_bfloat16* __restrict__ SHo, __nv_bfloat16* __restrict__ SLo,
           int M, int N, int K, float alpha, const float* __restrict__ bias)
{
    extern __shared__ char smem[];
    const uint32_t sbase = smem_u32(smem);
    const int tid = threadIdx.x;
    const int wid = tid >> 5, lane = tid & 31;
    const int m0 = blockIdx.y * 128, n0 = blockIdx.x * 128;
    const int mw = (wid & 1) * 64, nw = (wid >> 1) * 32;
    const int TOT = K >> 6;

    float acc[4][4][4];
#pragma unroll
    for (int i = 0; i < 4; i++)
#pragma unroll
        for (int j = 0; j < 4; j++)
#pragma unroll
            for (int l = 0; l < 4; l++) acc[i][j][l] = 0.f;

    auto issue = [&](int it) {
        const int k0 = it << 6;
        const uint32_t st = sbase + (uint32_t)(it % 3) * 65536u;
#pragma unroll
        for (int l = 0; l < 4; l++) {
            int c = tid + (l << 8);
            int row = c >> 3;
            uint32_t dst = sw128((uint32_t)(row << 7) + ((c & 7) << 4));
            int el = (c & 7) << 3;
            size_t ao = (size_t)(m0 + row) * K + k0 + el;
            size_t bo = (size_t)(n0 + row) * K + k0 + el;
            cpasync16(st + dst,         AHp + ao);
            cpasync16(st + 16384 + dst, ALp + ao);
            cpasync16(st + 32768 + dst, BHp + bo);
            cpasync16(st + 49152 + dst, BLp + bo);
        }
        asm volatile("cp.async.commit_group;" ::: "memory");
    };

    issue(0);
    if (TOT > 1) issue(1);
    for (int it = 0; it < TOT; it++) {
        if (it + 1 < TOT) {
            asm volatile("cp.async.wait_group 1;" ::: "memory");
        } else {
            asm volatile("cp.async.wait_group 0;" ::: "memory");
        }
        __syncthreads();
        const uint32_t st = sbase + (uint32_t)(it % 3) * 65536u;
#pragma unroll
        for (int ks = 0; ks < 4; ks++) {
            uint32_t afH[4][4], afL[4][4], bfH[4][2], bfL[4][2];
#pragma unroll
            for (int mf = 0; mf < 4; mf++) {
                int row = mw + mf * 16 + (lane & 15);
                uint32_t bo = (uint32_t)(row << 7) + (uint32_t)(ks << 5) + ((lane >> 4) << 4);
                uint32_t so = sw128(bo);
                ldsm_x4(afH[mf], st + so);
                ldsm_x4(afL[mf], st + 16384 + so);
            }
#pragma unroll
            for (int half = 0; half < 2; half++) {
                int i2 = lane >> 3;
                int row = nw + half * 16 + ((i2 >> 1) << 3) + (lane & 7);
                uint32_t bo = (uint32_t)(row << 7) + (uint32_t)(ks << 5) + ((i2 & 1) << 4);
                uint32_t so = sw128(bo);
                uint32_t r[4];
                ldsm_x4(r, st + 32768 + so);
                bfH[half * 2][0] = r[0];     bfH[half * 2][1] = r[1];
                bfH[half * 2 + 1][0] = r[2]; bfH[half * 2 + 1][1] = r[3];
                ldsm_x4(r, st + 49152 + so);
                bfL[half * 2][0] = r[0];     bfL[half * 2][1] = r[1];
                bfL[half * 2 + 1][0] = r[2]; bfL[half * 2 + 1][1] = r[3];
            }
#pragma unroll
            for (int mf = 0; mf < 4; mf++)
#pragma unroll
                for (int nf = 0; nf < 4; nf++) {
                    mma16816(acc[mf][nf], afH[mf], bfH[nf]);
                    mma16816(acc[mf][nf], afH[mf], bfL[nf]);
                    mma16816(acc[mf][nf], afL[mf], bfH[nf]);
                }
        }
        if (it + 2 < TOT) issue(it + 2);
    }

    const int rb = m0 + mw + (lane >> 2);
    const int cb = n0 + nw + ((lane & 3) << 1);
#pragma unroll
    for (int mf = 0; mf < 4; mf++) {
#pragma unroll
        for (int half = 0; half < 2; half++) {
            int row = rb + mf * 16 + half * 8;
#pragma unroll
            for (int nf = 0; nf < 4; nf++) {
                int col = cb + nf * 8;
                float vx = alpha * acc[mf][nf][half * 2 + 0];
                float vy = alpha * acc[mf][nf][half * 2 + 1];
                if (bias) { vx += bias[col]; vy += bias[col + 1]; }
                if (C) {
                    float2 v; v.x = vx; v.y = vy;
                    *(float2*)(C + (size_t)row * N + col) = v;
                }
                if (SHo) {
                    __nv_bfloat16 h0 = __float2bfloat16(vx);
                    __nv_bfloat16 h1 = __float2bfloat16(vy);
                    __nv_bfloat16 l0 = __float2bfloat16(vx - __bfloat162float(h0));
                    __nv_bfloat16 l1 = __float2bfloat16(vy - __bfloat162float(h1));
                    *(__nv_bfloat162*)(SHo + (size_t)row * N + col) = __nv_bfloat162(h0, h1);
                    *(__nv_bfloat162*)(SLo + (size_t)row * N + col) = __nv_bfloat162(l0, l1);
                }
            }
        }
    }
}

// ======================================================================
// A-chunk kernel (verified): A = qd @ kexp^T, tril, split to bf16.
// ======================================================================
__global__ __launch_bounds__(256, 1)
void akernel(const __nv_bfloat16* __restrict__ QH, const __nv_bfloat16* __restrict__ QL,
             const __nv_bfloat16* __restrict__ KH, const __nv_bfloat16* __restrict__ KL,
             __nv_bfloat16* __restrict__ AH, __nv_bfloat16* __restrict__ AL)
{
    extern __shared__ char smemc[];
    const uint32_t sb = smem_u32(smemc);
    const uint32_t oQH = 0, oQL = 32768, oKH = 65536, oKL = 98304;
    const int tid = threadIdx.x;
    const int wid = tid >> 5, lane = tid & 31;
    const int h = blockIdx.x, ch = blockIdx.y, bb = blockIdx.z;
    const int m0 = bb * TT + ch * CHUNK;
    const int colQ = h * 128;
    const size_t chA = (size_t)((bb * NCH + ch) * HH + h) * 16384;

#pragma unroll
    for (int l = 0; l < 8; l++) {
        int idx = tid + (l << 8);
        int row = idx >> 4, u = idx & 15;
        int kb = u >> 3, sub = u & 7;
        uint32_t dst = (uint32_t)kb * 16384u + sw128((uint32_t)(row << 7) + (sub << 4));
        size_t so = (size_t)(m0 + row) * DHALF + colQ + kb * 64 + sub * 8;
        cpasync16(sb + oQH + dst, QH + so);
        cpasync16(sb + oQL + dst, QL + so);
        cpasync16(sb + oKH + dst, KH + so);
        cpasync16(sb + oKL + dst, KL + so);
    }
    asm volatile("cp.async.commit_group;" ::: "memory");
    asm volatile("cp.async.wait_group 0;" ::: "memory");
    __syncthreads();

    const int mw = (wid & 1) * 64, nw = (wid >> 1) * 32;
    float acc[4][4][4];
#pragma unroll
    for (int i = 0; i < 4; i++)
#pragma unroll
        for (int j = 0; j < 4; j++)
#pragma unroll
            for (int l = 0; l < 4; l++) acc[i][j][l] = 0.f;

    mma_combo<4>(acc, sb + oQH, 16384, sb + oKH, 16384, mw, nw, lane);
    mma_combo<4>(acc, sb + oQH, 16384, sb + oKL, 16384, mw, nw, lane);
    mma_combo<4>(acc, sb + oQL, 16384, sb + oKH, 16384, mw, nw, lane);

#pragma unroll
    for (int mf = 0; mf < 4; mf++) {
#pragma unroll
        for (int half = 0; half < 2; half++) {
            int i = mw + mf * 16 + half * 8 + (lane >> 2);
#pragma unroll
            for (int nf = 0; nf < 4; nf++) {
                int j = nw + nf * 8 + ((lane & 3) << 1);
                float v0 = (j     <= i) ? acc[mf][nf][half * 2 + 0] : 0.f;
                float v1 = (j + 1 <= i) ? acc[mf][nf][half * 2 + 1] : 0.f;
                __nv_bfloat16 h0 = __float2bfloat16(v0);
                __nv_bfloat16 h1 = __float2bfloat16(v1);
                __nv_bfloat16 l0 = __float2bfloat16(v0 - __bfloat162float(h0));
                __nv_bfloat16 l1 = __float2bfloat16(v1 - __bfloat162float(h1));
                size_t oi = chA + (size_t)i * 128 + j;
                *(__nv_bfloat162*)(AH + oi) = __nv_bfloat162(h0, h1);
                *(__nv_bfloat162*)(AL + oi) = __nv_bfloat162(l0, l1);
            }
        }
    }
}

// ======================================================================
// state_kernel: serial S recurrence per (b,h,dv64) -> pre-update S^T blobs
// ======================================================================
__global__ __launch_bounds__(256, 1)
void state_kernel(const __nv_bfloat16* __restrict__ KDH, const __nv_bfloat16* __restrict__ KDL,
                  const __nv_bfloat16* __restrict__ VH, const __nv_bfloat16* __restrict__ VL,
                  const float* __restrict__ DEC,
                  __nv_bfloat16* __restrict__ SBH, __nv_bfloat16* __restrict__ SBL)
{
    extern __shared__ char smemc[];
    const uint32_t sb = smem_u32(smemc);
    const uint32_t oKT = 0, oKTl = 32768, oVH = 65536, oVL = 81920;
    const uint32_t oSC = 98304, oSCl = 114688, oS32 = 131072;
    float* ST32 = (float*)(smemc + oS32);           // [n=64][d=128]
    __shared__ float dec[128];

    const int tid = threadIdx.x;
    const int wid = tid >> 5, lane = tid & 31;
    const int vsl = blockIdx.x, h = blockIdx.y, bb = blockIdx.z;
    const int colQ = h * 128;
    const int colV = h * 256 + vsl * 64;
    const int mw = (wid & 3) * 32, nw = (wid >> 2) * 32;
    const int blobbase = ((bb * HH + h) * 4 + vsl) * NCH;

    for (int i = tid; i < 8192; i += 256) ST32[i] = 0.f;

    for (int ch = 0; ch < NCH; ch++) {
        const int m0 = bb * TT + ch * CHUNK;
        __syncthreads();

#pragma unroll
        for (int l = 0; l < 32; l++) {
            int idx = tid + (l << 8);
            int j = idx >> 6, d = (idx & 63) << 1;
            uint32_t wv = *(const uint32_t*)(KDH + (size_t)(m0 + j) * DHALF + colQ + d);
            uint32_t wl = *(const uint32_t*)(KDL + (size_t)(m0 + j) * DHALF + colQ + d);
            uint32_t kbo = (uint32_t)(j >> 6) * 16384u;
            uint32_t off0 = kbo + sw128((uint32_t)(d << 7) + ((j & 63) << 1));
            uint32_t off1 = kbo + sw128((uint32_t)((d + 1) << 7) + ((j & 63) << 1));
            *(unsigned short*)(smemc + oKT  + off0) = (unsigned short)(wv & 0xffff);
            *(unsigned short*)(smemc + oKT  + off1) = (unsigned short)(wv >> 16);
            *(unsigned short*)(smemc + oKTl + off0) = (unsigned short)(wl & 0xffff);
            *(unsigned short*)(smemc + oKTl + off1) = (unsigned short)(wl >> 16);
        }
#pragma unroll
        for (int l = 0; l < 16; l++) {
            int idx = tid + (l << 8);
            int j = idx >> 5, n = (idx & 31) << 1;
            uint32_t wv = *(const uint32_t*)(VH + (size_t)(m0 + j) * DD + colV + n);
            uint32_t wl = *(const uint32_t*)(VL + (size_t)(m0 + j) * DD + colV + n);
            uint32_t kbo = (uint32_t)(j >> 6) * 8192u;
            uint32_t off0 = kbo + sw128((uint32_t)(n << 7) + ((j & 63) << 1));
            uint32_t off1 = kbo + sw128((uint32_t)((n + 1) << 7) + ((j & 63) << 1));
            *(unsigned short*)(smemc + oVH + off0) = (unsigned short)(wv & 0xffff);
            *(unsigned short*)(smemc + oVH + off1) = (unsigned short)(wv >> 16);
            *(unsigned short*)(smemc + oVL + off0) = (unsigned short)(wl & 0xffff);
            *(unsigned short*)(smemc + oVL + off1) = (unsigned short)(wl >> 16);
        }
        for (int i = tid; i < 8192; i += 256) {
            int n = i >> 7, d = i & 127;
            float v = ST32[i];
            __nv_bfloat16 hv = __float2bfloat16(v);
            __nv_bfloat16 lv = __float2bfloat16(v - __bfloat162float(hv));
            uint32_t off = (uint32_t)(d >> 6) * 8192u + sw128((uint32_t)(n << 7) + ((d & 63) << 1));
            *(__nv_bfloat16*)(smemc + oSC  + off) = hv;
            *(__nv_bfloat16*)(smemc + oSCl + off) = lv;
        }
        if (tid < 128) dec[tid] = DEC[(size_t)(bb * NCH + ch) * DHALF + colQ + tid];
        __syncthreads();

        {
            const float4* sH = (const float4*)(smemc + oSC);
            const float4* sL = (const float4*)(smemc + oSCl);
            float4* dH = (float4*)(SBH + (size_t)(blobbase + ch) * 8192);
            float4* dL = (float4*)(SBL + (size_t)(blobbase + ch) * 8192);
            for (int i = tid; i < 1024; i += 256) { dH[i] = sH[i]; dL[i] = sL[i]; }
        }

        float sacc[2][4][4];
#pragma unroll
        for (int i = 0; i < 2; i++)
#pragma unroll
            for (int j = 0; j < 4; j++)
#pragma unroll
                for (int l = 0; l < 4; l++) sacc[i][j][l] = 0.f;

        mma_combo<2>(sacc, sb + oKT,  16384, sb + oVH, 8192, mw, nw, lane);
        mma_combo<2>(sacc, sb + oKT,  16384, sb + oVL, 8192, mw, nw, lane);
        mma_combo<2>(sacc, sb + oKTl, 16384, sb + oVH, 8192, mw, nw, lane);

#pragma unroll
        for (int mf = 0; mf < 2; mf++) {
#pragma unroll
            for (int half = 0; half < 2; half++) {
                int d = mw + mf * 16 + half * 8 + (lane >> 2);
                float dv = dec[d];
#pragma unroll
                for (int nf = 0; nf < 4; nf++) {
                    int n = nw + nf * 8 + ((lane & 3) << 1);
                    int i0 = n * 128 + d, i1 = (n + 1) * 128 + d;
                    ST32[i0] = dv * ST32[i0] + sacc[mf][nf][half * 2 + 0];
                    ST32[i1] = dv * ST32[i1] + sacc[mf][nf][half * 2 + 1];
                }
            }
        }
    }
}

// ======================================================================
// o_kernel: fully parallel O phase. block per (b,h,ch,dv64).
// ======================================================================
__global__ __launch_bounds__(256, 1)
void o_kernel(const __nv_bfloat16* __restrict__ QH, const __nv_bfloat16* __restrict__ QL,
              const __nv_bfloat16* __restrict__ AH, const __nv_bfloat16* __restrict__ AL,
              const __nv_bfloat16* __restrict__ VH, const __nv_bfloat16* __restrict__ VL,
              const __nv_bfloat16* __restrict__ SBH, const __nv_bfloat16* __restrict__ SBL,
              float* __restrict__ O)
{
    extern __shared__ char smemc[];
    const uint32_t sb = smem_u32(smemc);
    const uint32_t oQH = 0, oQL = 32768, oAH = 65536, oAL = 98304;
    const uint32_t oVH = 131072, oVL = 147456, oSH = 163840, oSL = 180224;

    const int tid = threadIdx.x;
    const int wid = tid >> 5, lane = tid & 31;
    const int ch = blockIdx.x >> 2, vsl = blockIdx.x & 3;
    const int h = blockIdx.y, bb = blockIdx.z;
    const int m0 = bb * TT + ch * CHUNK;
    const int colQ = h * 128;
    const int colV = h * 256 + vsl * 64;
    const size_t chA = (size_t)((bb * NCH + ch) * HH + h) * 16384;
    const size_t blob = (size_t)(((bb * HH + h) * 4 + vsl) * NCH + ch) * 8192;
    const int mw = (wid & 3) * 32, nw = (wid >> 2) * 32;

#pragma unroll
    for (int l = 0; l < 8; l++) {
        int idx = tid + (l << 8);
        int row = idx >> 4, u = idx & 15;
        int kb = u >> 3, sub = u & 7;
        uint32_t dst = (uint32_t)kb * 16384u + sw128((uint32_t)(row << 7) + (sub << 4));
        size_t so = (size_t)(m0 + row) * DHALF + colQ + kb * 64 + sub * 8;
        cpasync16(sb + oQH + dst, QH + so);
        cpasync16(sb + oQL + dst, QL + so);
        size_t sa = chA + (size_t)row * 128 + kb * 64 + sub * 8;
        cpasync16(sb + oAH + dst, AH + sa);
        cpasync16(sb + oAL + dst, AL + sa);
    }
#pragma unroll
    for (int l = 0; l < 4; l++) {
        int i = tid + (l << 8);
        cpasync16(sb + oSH + (i << 4), SBH + blob + (size_t)i * 8);
        cpasync16(sb + oSL + (i << 4), SBL + blob + (size_t)i * 8);
    }
    asm volatile("cp.async.commit_group;" ::: "memory");

#pragma unroll
    for (int l = 0; l < 16; l++) {
        int idx = tid + (l << 8);
        int j = idx >> 5, n = (idx & 31) << 1;
        uint32_t wv = *(const uint32_t*)(VH + (size_t)(m0 + j) * DD + colV + n);
        uint32_t wl = *(const uint32_t*)(VL + (size_t)(m0 + j) * DD + colV + n);
        uint32_t kbo = (uint32_t)(j >> 6) * 8192u;
        uint32_t off0 = kbo + sw128((uint32_t)(n << 7) + ((j & 63) << 1));
        uint32_t off1 = kbo + sw128((uint32_t)((n + 1) << 7) + ((j & 63) << 1));
        *(unsigned short*)(smemc + oVH + off0) = (unsigned short)(wv & 0xffff);
        *(unsigned short*)(smemc + oVH + off1) = (unsigned short)(wv >> 16);
        *(unsigned short*)(smemc + oVL + off0) = (unsigned short)(wl & 0xffff);
        *(unsigned short*)(smemc + oVL + off1) = (unsigned short)(wl >> 16);
    }
    asm volatile("cp.async.wait_group 0;" ::: "memory");
    __syncthreads();

    float acc[2][4][4];
#pragma unroll
    for (int i = 0; i < 2; i++)
#pragma unroll
        for (int j = 0; j < 4; j++)
#pragma unroll
            for (int l = 0; l < 4; l++) acc[i][j][l] = 0.f;

    mma_combo<2>(acc, sb + oAH, 16384, sb + oVH, 8192, mw, nw, lane);
    mma_combo<2>(acc, sb + oAH, 16384, sb + oVL, 8192, mw, nw, lane);
    mma_combo<2>(acc, sb + oAL, 16384, sb + oVH, 8192, mw, nw, lane);
    mma_combo<2>(acc, sb + oQH, 16384, sb + oSH, 8192, mw, nw, lane);
    mma_combo<2>(acc, sb + oQH, 16384, sb + oSL, 8192, mw, nw, lane);
    mma_combo<2>(acc, sb + oQL, 16384, sb + oSH, 8192, mw, nw, lane);

#pragma unroll
    for (int mf = 0; mf < 2; mf++) {
#pragma unroll
        for (int half = 0; half < 2; half++) {
            int row = m0 + mw + mf * 16 + half * 8 + (lane >> 2);
#pragma unroll
            for (int nf = 0; nf < 4; nf++) {
                int col = colV + nw + nf * 8 + ((lane & 3) << 1);
                float2 v;
                v.x = acc[mf][nf][half * 2 + 0];
                v.y = acc[mf][nf][half * 2 + 1];
                *(float2*)&O[(size_t)row * DD + col] = v;
            }
        }
    }
}

// ======================================================================
// split x -> bf16 hi/lo
// ======================================================================
__global__ void xsplit(const float4* __restrict__ X, __nv_bfloat16* __restrict__ H,
                       __nv_bfloat16* __restrict__ L, int n4)
{
    int i = blockIdx.x * blockDim.x + threadIdx.x;
    if (i >= n4) return;
    float4 v = X[i];
    __nv_bfloat16 h0 = __float2bfloat16(v.x), h1 = __float2bfloat16(v.y);
    __nv_bfloat16 h2 = __float2bfloat16(v.z), h3 = __float2bfloat16(v.w);
    __nv_bfloat16 l0 = __float2bfloat16(v.x - __bfloat162float(h0));
    __nv_bfloat16 l1 = __float2bfloat16(v.y - __bfloat162float(h1));
    __nv_bfloat16 l2 = __float2bfloat16(v.z - __bfloat162float(h2));
    __nv_bfloat16 l3 = __float2bfloat16(v.w - __bfloat162float(h3));
    __nv_bfloat162* Hp = (__nv_bfloat162*)H;
    __nv_bfloat162* Lp = (__nv_bfloat162*)L;
    Hp[i * 2]     = __nv_bfloat162(h0, h1);
    Hp[i * 2 + 1] = __nv_bfloat162(h2, h3);
    Lp[i * 2]     = __nv_bfloat162(l0, l1);
    Lp[i * 2 + 1] = __nv_bfloat162(l2, l3);
}

// ======================================================================
// transpose W [K,N] -> combined WT buffer rows [rowoff..rowoff+N), x alpha
// ======================================================================
__global__ void wsplit_t(const float* __restrict__ W, __nv_bfloat16* __restrict__ Th,
                         __nv_bfloat16* __restrict__ Tl, int K, int N, int rowoff, float alpha)
{
    __shared__ float t[32][33];
    const int n0 = blockIdx.x * 32, k0 = blockIdx.y * 32;
    const int tx = threadIdx.x, ty = threadIdx.y;
#pragma unroll
    for (int i = 0; i < 4; i++) {
        int k = ty + i * 8;
        t[k][tx] = W[(size_t)(k0 + k) * N + n0 + tx];
    }
    __syncthreads();
#pragma unroll
    for (int i = 0; i < 4; i++) {
        int n = ty + i * 8;
        float v = t[tx][n] * alpha;
        __nv_bfloat16 h = __float2bfloat16(v);
        size_t oi = (size_t)(rowoff + n0 + n) * K + k0 + tx;
        Th[oi] = h;
        Tl[oi] = __float2bfloat16(v - __bfloat162float(h));
    }
}

// ======================================================================
// kg1: out[M,16] = x @ Wkg1. warp per row.
// ======================================================================
__global__ void kg1_kernel(const float* __restrict__ x, const float* __restrict__ W1,
                           float* __restrict__ out)
{
    const int wid = threadIdx.x >> 5, lane = threadIdx.x & 31;
    const int row = blockIdx.x * 8 + wid;
    const float* xp = x + (size_t)row * DD;
    float acc[16];
#pragma unroll
    for (int c = 0; c < 16; c++) acc[c] = 0.f;
    for (int k = lane; k < DD; k += 32) {
        float xv = xp[k];
        const float4* wp = (const float4*)(W1 + (size_t)k * 16);
        float4 w0 = wp[0], w1 = wp[1], w2 = wp[2], w3 = wp[3];
        acc[0]  += xv * w0.x; acc[1]  += xv * w0.y; acc[2]  += xv * w0.z; acc[3]  += xv * w0.w;
        acc[4]  += xv * w1.x; acc[5]  += xv * w1.y; acc[6]  += xv * w1.z; acc[7]  += xv * w1.w;
        acc[8]  += xv * w2.x; acc[9]  += xv * w2.y; acc[10] += xv * w2.z; acc[11] += xv * w2.w;
        acc[12] += xv * w3.x; acc[13] += xv * w3.y; acc[14] += xv * w3.z; acc[15] += xv * w3.w;
    }
#pragma unroll
    for (int c = 0; c < 16; c++) {
        float v = acc[c];
#pragma unroll
        for (int off = 16; off; off >>= 1) v += __shfl_xor_sync(0xFFFFFFFFu, v, off);
        if (lane == 0) out[(size_t)row * 16 + c] = v;
    }
}

// ======================================================================
// gk = log_sigmoid(KG1 @ Wkg2 + bkg2) / 16
// ======================================================================
__global__ void gk_kernel(const float* __restrict__ KG1,
                          const float* __restrict__ W2,
                          const float* __restrict__ b2,
                          float* __restrict__ GK)
{
    __shared__ float a[16];
    int m = blockIdx.x;
    if (threadIdx.x < 16) a[threadIdx.x] = KG1[(size_t)m * 16 + threadIdx.x];
    __syncthreads();
    for (int c = threadIdx.x; c < DHALF; c += 128) {
        float z = b2[c];
#pragma unroll
        for (int r = 0; r < 16; r++) z = fmaf(a[r], W2[(size_t)r * DHALF + c], z);
        float ls = (z >= 0.f) ? -log1pf(expf(-z)) : (z - log1pf(expf(z)));
        GK[(size_t)m * DHALF + c] = ls * INV_NORM_GK;
    }
}

// ======================================================================
// decay precompute (reads combined QK buffer, stride 2048)
// ======================================================================
__global__ void prep_kernel(const float* __restrict__ QK,
                            const float* __restrict__ GK,
                            __nv_bfloat16* __restrict__ QHo, __nv_bfloat16* __restrict__ QLo,
                            __nv_bfloat16* __restrict__ KHo, __nv_bfloat16* __restrict__ KLo,
                            __nv_bfloat16* __restrict__ KDHo, __nv_bfloat16* __restrict__ KDLo,
                            float* __restrict__ DEC)
{
    int g = blockIdx.x * blockDim.x + threadIdx.x;
    int col = g & (DHALF - 1);
    int bc  = g >> 10;
    int row0 = ((bc >> 4) * TT) + ((bc & 15) * CHUNK);
    size_t baseg = (size_t)row0 * DHALF + col;
    size_t baseq = (size_t)row0 * 2048 + col;

    float gs = 0.f;
#pragma unroll 4
    for (int i = 0; i < CHUNK; i++) gs += GK[baseg + (size_t)i * DHALF];

    float gc = 0.f;
    for (int i = 0; i < CHUNK; i++) {
        size_t idx = baseg + (size_t)i * DHALF;
        size_t qdx = baseq + (size_t)i * 2048;
        gc += GK[idx];
        float qd = QK[qdx] * expf(gc);
        float kv = QK[qdx + 1024];
        float ke = kv * expf(-gc);
        float kd = kv * expf(gs - gc);
        __nv_bfloat16 qh = __float2bfloat16(qd);
        __nv_bfloat16 kh = __float2bfloat16(ke);
        __nv_bfloat16 dh = __float2bfloat16(kd);
        QHo[idx]  = qh; QLo[idx]  = __float2bfloat16(qd - __bfloat162float(qh));
        KHo[idx]  = kh; KLo[idx]  = __float2bfloat16(ke - __bfloat162float(kh));
        KDHo[idx] = dh; KDLo[idx] = __float2bfloat16(kd - __bfloat162float(dh));
    }
    DEC[(size_t)bc * DHALF + col] = expf(gs);
}

// ======================================================================
// GroupNorm(256) * silu(g) -> bf16 hi/lo split
// ======================================================================
__global__ void norm_gate_kernel(const float* __restrict__ O,
                                 const float* __restrict__ G,
                                 __nv_bfloat16* __restrict__ PH,
                                 __nv_bfloat16* __restrict__ PL)
{
    int m = blockIdx.x, h = blockIdx.y;
    int tid = threadIdx.x;
    size_t idx = (size_t)m * DD + h * DV + tid;
    float v = O[idx];
    float s = v, s2 = v * v;
#pragma unroll
    for (int off = 16; off; off >>= 1) {
        s  += __shfl_xor_sync(0xFFFFFFFFu, s,  off);
        s2 += __shfl_xor_sync(0xFFFFFFFFu, s2, off);
    }
    __shared__ float ws[8], ws2[8];
    int w = tid >> 5, l = tid & 31;
    if (l == 0) { ws[w] = s; ws2[w] = s2; }
    __syncthreads();
    float ts = 0.f, ts2 = 0.f;
#pragma unroll
    for (int i = 0; i < 8; i++) { ts += ws[i]; ts2 += ws2[i]; }
    float mu = ts * (1.f / 256.f);
    float var = ts2 * (1.f / 256.f) - mu * mu;
    float nv = (v - mu) * rsqrtf(var + 1e-5f);
    float gt = G[idx];
    float sg = gt / (1.f + expf(-gt));
    float val = sg * nv;
    __nv_bfloat16 hh = __float2bfloat16(val);
    PH[idx] = hh;
    PL[idx] = __float2bfloat16(val - __bfloat162float(hh));
}

// ======================================================================
extern "C" void kernel_launch(void* const* d_in, const int* in_sizes, int n_in,
                              void* d_out, int out_size)
{
    const float* x    = (const float*)d_in[0];
    const float* Wq   = (const float*)d_in[1];
    const float* Wk   = (const float*)d_in[2];
    const float* Wkg1 = (const float*)d_in[3];
    const float* Wkg2 = (const float*)d_in[4];
    const float* bkg2 = (const float*)d_in[5];
    const float* Wv   = (const float*)d_in[6];
    const float* Wg   = (const float*)d_in[7];
    const float* bg   = (const float*)d_in[8];
    const float* Wo   = (const float*)d_in[9];
    float* out = (float*)d_out;

    float *pQK, *pGK, *pKG1, *pDEC, *pG, *pO;
    __nv_bfloat16 *pXH, *pXL, *pWTH, *pWTL, *pPH, *pPL;
    __nv_bfloat16 *pQH, *pQL, *pKH, *pKL, *pKDH, *pKDL, *pVH, *pVL, *pAH, *pAL, *pSBH, *pSBL;
    cudaGetSymbolAddress((void**)&pQK,  g_QK);
    cudaGetSymbolAddress((void**)&pGK,  g_GK);
    cudaGetSymbolAddress((void**)&pKG1, g_KG1);
    cudaGetSymbolAddress((void**)&pDEC, g_DEC);
    cudaGetSymbolAddress((void**)&pG,   g_G);
    cudaGetSymbolAddress((void**)&pO,   g_O);
    cudaGetSymbolAddress((void**)&pXH,  g_XH);
    cudaGetSymbolAddress((void**)&pXL,  g_XL);
    cudaGetSymbolAddress((void**)&pWTH, g_WTH);
    cudaGetSymbolAddress((void**)&pWTL, g_WTL);
    cudaGetSymbolAddress((void**)&pPH,  g_PH);
    cudaGetSymbolAddress((void**)&pPL,  g_PL);
    cudaGetSymbolAddress((void**)&pQH,  g_QH);
    cudaGetSymbolAddress((void**)&pQL,  g_QL);
    cudaGetSymbolAddress((void**)&pKH,  g_KH);
    cudaGetSymbolAddress((void**)&pKL,  g_KL);
    cudaGetSymbolAddress((void**)&pKDH, g_KDH);
    cudaGetSymbolAddress((void**)&pKDL, g_KDL);
    cudaGetSymbolAddress((void**)&pVH,  g_VH);
    cudaGetSymbolAddress((void**)&pVL,  g_VL);
    cudaGetSymbolAddress((void**)&pAH,  g_AH);
    cudaGetSymbolAddress((void**)&pAL,  g_AL);
    cudaGetSymbolAddress((void**)&pSBH, g_SBH);
    cudaGetSymbolAddress((void**)&pSBL, g_SBL);

    cudaFuncSetAttribute(gemm3,        cudaFuncAttributeMaxDynamicSharedMemorySize, 196608);
    cudaFuncSetAttribute(akernel,      cudaFuncAttributeMaxDynamicSharedMemorySize, 131072);
    cudaFuncSetAttribute(state_kernel, cudaFuncAttributeMaxDynamicSharedMemorySize, 163840);
    cudaFuncSetAttribute(o_kernel,     cudaFuncAttributeMaxDynamicSharedMemorySize, 196608);

    dim3 tb(32, 8);
    int n4 = MROWS * DD / 4;

    // splits of x and all weights (combined WT buffer: Q|K*scale|V|G|O)
    xsplit<<<(n4 + 255) / 256, 256>>>((const float4*)x, pXH, pXL, n4);
    kg1_kernel<<<MROWS / 8, 256>>>(x, Wkg1, pKG1);
    wsplit_t<<<dim3(DHALF / 32, DD / 32), tb>>>(Wq, pWTH, pWTL, DD, DHALF, 0, 1.0f);
    wsplit_t<<<dim3(DHALF / 32, DD / 32), tb>>>(Wk, pWTH, pWTL, DD, DHALF, 1024, SCALING);
    wsplit_t<<<dim3(DD / 32, DD / 32), tb>>>(Wv, pWTH, pWTL, DD, DD, 2048, 1.0f);
    wsplit_t<<<dim3(DD / 32, DD / 32), tb>>>(Wg, pWTH, pWTL, DD, DD, 4096, 1.0f);
    wsplit_t<<<dim3(DD / 32, DD / 32), tb>>>(Wo, pWTH, pWTL, DD, DD, 6144, 1.0f);

    // fused Q+K projection (N=2048)
    gemm3<<<dim3(2048 / 128, MROWS / 128), 256, 196608>>>(pXH, pXL, pWTH, pWTL,
        pQK, nullptr, nullptr, MROWS, 2048, DD, 1.0f, nullptr);

    // gk + decay precompute
    gk_kernel<<<MROWS, 128>>>(pKG1, Wkg2, bkg2, pGK);
    prep_kernel<<<256, 256>>>(pQK, pGK, pQH, pQL, pKH, pKL, pKDH, pKDL, pDEC);

    // A chunks
    akernel<<<dim3(HH, NCH, BB), 256, 131072>>>(pQH, pQL, pKH, pKL, pAH, pAL);

    // V projection -> bf16 split directly
    gemm3<<<dim3(DD / 128, MROWS / 128), 256, 196608>>>(pXH, pXL,
        pWTH + (size_t)2048 * DD, pWTL + (size_t)2048 * DD,
        nullptr, pVH, pVL, MROWS, DD, DD, 1.0f, nullptr);

    // serial state recurrence -> S blobs
    state_kernel<<<dim3(4, HH, BB), 256, 163840>>>(pKDH, pKDL, pVH, pVL, pDEC, pSBH, pSBL);

    // G projection (+bias)
    gemm3<<<dim3(DD / 128, MROWS / 128), 256, 196608>>>(pXH, pXL,
        pWTH + (size_t)4096 * DD, pWTL + (size_t)4096 * DD,
        pG, nullptr, nullptr, MROWS, DD, DD, 1.0f, bg);

    // parallel O phase
    o_kernel<<<dim3(NCH * 4, HH, BB), 256, 196608>>>(pQH, pQL, pAH, pAL, pVH, pVL,
                                                     pSBH, pSBL, pO);

    // groupnorm + silu gate -> bf16 split
    norm_gate_kernel<<<dim3(MROWS, HH), 256>>>(pO, pG, pPH, pPL);

    // output projection
    gemm3<<<dim3(DD / 128, MROWS / 128), 256, 196608>>>(pPH, pPL,
        pWTH + (size_t)6144 * DD, pWTL + (size_t)6144 * DD,
        out, nullptr, nullptr, MROWS, DD, DD, 1.0f, nullptr);
}